// round 6
// baseline (speedup 1.0000x reference)
#include <cuda_runtime.h>
#include <math.h>

#define B_    32
#define T_IN  1024
#define CIN   128
#define F_    256
#define TC    510
#define H_    512
#define G4    2048
#define M_    (TC*B_)
#define NCTA3 128

__device__ float g_wt[5*CIN*F_];
__device__ float g_y[(size_t)M_*F_];
__device__ float g_xp[(size_t)TC*G4*B_];
__device__ float g_h[2][B_*H_];
__device__ float g_udot[2][NCTA3][B_];
__device__ unsigned g_arr[NCTA3];

typedef unsigned long long ull;

__device__ __forceinline__ ull fma2(ull a, ull b, ull c) {
    ull d;
    asm("fma.rn.f32x2 %0, %1, %2, %3;" : "=l"(d) : "l"(a), "l"(b), "l"(c));
    return d;
}
__device__ __forceinline__ ull add2(ull a, ull b) {
    ull d;
    asm("add.rn.f32x2 %0, %1, %2;" : "=l"(d) : "l"(a), "l"(b));
    return d;
}
__device__ __forceinline__ unsigned ldvol(const unsigned* p) {
    unsigned v;
    asm volatile("ld.global.cg.u32 %0, [%1];" : "=r"(v) : "l"(p));
    return v;
}

__global__ void k0_wt(const float* __restrict__ cw) {
    int k = blockIdx.x, f = threadIdx.x;
    g_wt[(size_t)k*F_ + f] = cw[((size_t)f*CIN + (k & 127))*5 + (k >> 7)];
}

__global__ __launch_bounds__(256) void k1_conv(
    const float* __restrict__ x, const float* __restrict__ cb,
    const float* __restrict__ gamma, const float* __restrict__ beta,
    const float* __restrict__ mean, const float* __restrict__ var)
{
    __shared__ float As[16][132];
    __shared__ float Bs[16][132];
    const int n0 = blockIdx.x * 128, m0 = blockIdx.y * 128;
    const int tid = threadIdx.x, tx = tid & 15, ty = tid >> 4;
    float acc[8][8];
#pragma unroll
    for (int i = 0; i < 8; i++)
#pragma unroll
        for (int j = 0; j < 8; j++) acc[i][j] = 0.f;

    for (int ks = 0; ks < 40; ks++) {
        const int k0 = ks * 16;
#pragma unroll
        for (int i = 0; i < 2; i++) {
            int idx = tid + i*256, ml = idx >> 2, kc = (idx & 3)*4;
            int m = m0 + ml;
            float4 v = make_float4(0.f,0.f,0.f,0.f);
            if (m < M_) {
                int t = m >> 5, b = m & 31, k = k0 + kc;
                v = *(const float4*)(x + ((size_t)b*T_IN + (size_t)(2*t + (k>>7)))*CIN + (k&127));
            }
            As[kc][ml]=v.x; As[kc+1][ml]=v.y; As[kc+2][ml]=v.z; As[kc+3][ml]=v.w;
        }
#pragma unroll
        for (int i = 0; i < 2; i++) {
            int idx = tid + i*256, kr = idx >> 5, nc = (idx & 31)*4;
            float4 v = *(const float4*)(g_wt + (size_t)(k0+kr)*F_ + n0 + nc);
            Bs[kr][nc]=v.x; Bs[kr][nc+1]=v.y; Bs[kr][nc+2]=v.z; Bs[kr][nc+3]=v.w;
        }
        __syncthreads();
#pragma unroll
        for (int kk = 0; kk < 16; kk++) {
            float a[8], b[8];
            *(float4*)&a[0] = *(const float4*)&As[kk][ty*8];
            *(float4*)&a[4] = *(const float4*)&As[kk][ty*8+4];
            *(float4*)&b[0] = *(const float4*)&Bs[kk][tx*8];
            *(float4*)&b[4] = *(const float4*)&Bs[kk][tx*8+4];
#pragma unroll
            for (int i = 0; i < 8; i++)
#pragma unroll
                for (int j = 0; j < 8; j++) acc[i][j] = fmaf(a[i], b[j], acc[i][j]);
        }
        __syncthreads();
    }
    const int f0 = n0 + tx*8;
    float invs[8], adds[8], cbs[8];
#pragma unroll
    for (int j = 0; j < 8; j++) {
        float iv = gamma[f0+j] * rsqrtf(var[f0+j] + 1e-5f);
        invs[j] = iv; adds[j] = beta[f0+j] - mean[f0+j]*iv; cbs[j] = cb[f0+j];
    }
#pragma unroll
    for (int i = 0; i < 8; i++) {
        int m = m0 + ty*8 + i;
        if (m < M_) {
            float o[8];
#pragma unroll
            for (int j = 0; j < 8; j++)
                o[j] = fmaxf(acc[i][j] + cbs[j], 0.f)*invs[j] + adds[j];
            *(float4*)(g_y + (size_t)m*F_ + f0)   = make_float4(o[0],o[1],o[2],o[3]);
            *(float4*)(g_y + (size_t)m*F_ + f0+4) = make_float4(o[4],o[5],o[6],o[7]);
        }
    }
}

__global__ __launch_bounds__(256) void k2_xproj(
    const float* __restrict__ w_ih, const float* __restrict__ b_ih,
    const float* __restrict__ b_hh)
{
    extern __shared__ float sm2[];
    float* Ys = sm2;            // 32 x 257
    float* Ws = sm2 + 32*257;   // 32 x 128
    const int t = blockIdx.y, g0 = blockIdx.x * 128;
    const int tid = threadIdx.x, tx = tid & 15, ty = tid >> 4;

    const float* src = g_y + (size_t)t*32*F_;
#pragma unroll
    for (int q = 0; q < 8; q++) {
        int idx = tid + q*256, b = idx >> 6, f4 = idx & 63;
        float4 v = *(const float4*)(src + (size_t)b*F_ + f4*4);
        float* d = Ys + b*257 + f4*4;
        d[0]=v.x; d[1]=v.y; d[2]=v.z; d[3]=v.w;
    }
    float acc[8][2];
#pragma unroll
    for (int j = 0; j < 8; j++) { acc[j][0]=0.f; acc[j][1]=0.f; }

    for (int fs = 0; fs < 8; fs++) {
        __syncthreads();
#pragma unroll
        for (int q = 0; q < 4; q++) {
            int idx = tid + q*256, g = idx >> 3, f4 = idx & 7;
            float4 v = *(const float4*)(w_ih + (size_t)(g0+g)*F_ + fs*32 + f4*4);
            Ws[(f4*4  )*128+g]=v.x; Ws[(f4*4+1)*128+g]=v.y;
            Ws[(f4*4+2)*128+g]=v.z; Ws[(f4*4+3)*128+g]=v.w;
        }
        __syncthreads();
#pragma unroll
        for (int fr = 0; fr < 32; fr++) {
            float a[8];
            *(float4*)&a[0] = *(const float4*)(Ws + fr*128 + ty*8);
            *(float4*)&a[4] = *(const float4*)(Ws + fr*128 + ty*8 + 4);
            float y0 = Ys[(tx*2  )*257 + fs*32 + fr];
            float y1 = Ys[(tx*2+1)*257 + fs*32 + fr];
#pragma unroll
            for (int j = 0; j < 8; j++) {
                acc[j][0] = fmaf(a[j], y0, acc[j][0]);
                acc[j][1] = fmaf(a[j], y1, acc[j][1]);
            }
        }
    }
#pragma unroll
    for (int j = 0; j < 8; j++) {
        int g = g0 + ty*8 + j;
        float bias = b_ih[g] + b_hh[g];
        size_t base = ((size_t)t*G4 + g)*B_ + tx*2;
        g_xp[base] = acc[j][0] + bias;
        g_xp[base+1] = acc[j][1] + bias;
    }
}

__device__ __forceinline__ float sigf(float v) { return 1.f/(1.f + __expf(-v)); }

// K3: 128 CTAs x 256 threads. Flag-vector grid barrier (no atomics).
__global__ void __launch_bounds__(256, 1) k3_lstm(
    const float* __restrict__ w_hh, const float* __restrict__ w_uh,
    const float* __restrict__ b_uh, float* __restrict__ dout)
{
    extern __shared__ float dsm[];
    float* whh_s = dsm;           // 16 x 512
    float* hs    = dsm + 16*512;  // 32 x 512
    __shared__ float gm[16][33];
    __shared__ float u_s[32], ubin_s[32];
    __shared__ float red[8][32];
    __shared__ float cpart[4][32];
    __shared__ float wuh_s[4];

    const int cta = blockIdx.x, tid = threadIdx.x;
    const int lane = tid & 31, wid = tid >> 5;

#pragma unroll
    for (int q = 0; q < 8; q++) {
        int i4 = tid + q*256;
        int r = i4 >> 7, kk = (i4 & 127)*4;
        int grow = (r >> 2)*512 + cta*4 + (r & 3);
        *(float4*)(whh_s + r*512 + kk) = *(const float4*)(w_hh + (size_t)grow*H_ + kk);
    }
    if (tid < 4) wuh_s[tid] = w_uh[cta*4 + tid];
    const float buh = b_uh[0];

    const int ggrp = wid >> 2;
    const int bq   = wid & 3;
    const int bcol = bq*8 + (lane & 7);
    const int r0 = ggrp*8 + (lane >> 3);
    const int r1 = r0 + 4;
    const int gr0 = (r0 >> 2)*512 + cta*4 + (r0 & 3);
    const int gr1 = (r1 >> 2)*512 + cta*4 + (r1 & 3);

    float c_reg = 0.f;
    __syncthreads();

    for (int t = 0; t < TC; ++t) {
        const int pp = t & 1, pq = pp ^ 1;

        if (t > 0) {
            {
                int b = tid & 31, ch = tid >> 5;
                const float* s8 = &g_udot[pq][ch*16][0];
                float s = 0.f;
#pragma unroll
                for (int c = 0; c < 16; c++) s += __ldcg(s8 + c*32 + b);
                red[ch][b] = s;
            }
            const float4* s4 = (const float4*)g_h[pq];
#pragma unroll
            for (int q = 0; q < 16; q++)
                *(float4*)(hs + (tid + q*256)*4) = __ldcg(s4 + tid + q*256);
            __syncthreads();
            if (tid < 32) {
                float tot = 0.f;
#pragma unroll
                for (int ch = 0; ch < 8; ch++) tot += red[ch][tid];
                float du = sigf(tot + buh);
                float up = u_s[tid], ub = ubin_s[tid];
                float un = ub*du + (1.f-ub)*(up + fminf(du, 1.f - up));
                u_s[tid] = un; ubin_s[tid] = rintf(un);
            }
        } else {
            float4 z = make_float4(0.f,0.f,0.f,0.f);
#pragma unroll
            for (int q = 0; q < 16; q++) *(float4*)(hs + (tid + q*256)*4) = z;
            if (tid < 32) { u_s[tid] = 1.f; ubin_s[tid] = 1.f; }
            __syncthreads();
        }

        float xv0 = __ldcg(g_xp + ((size_t)t*G4 + gr0)*B_ + bcol);
        float xv1 = __ldcg(g_xp + ((size_t)t*G4 + gr1)*B_ + bcol);

        ull acc[64];
#pragma unroll
        for (int j = 0; j < 64; j++) acc[j] = 0ULL;
#pragma unroll
        for (int i = 0; i < 4; i++) {
            const int kk = 4*lane + 128*i;
            ulonglong2 hv[8];
#pragma unroll
            for (int bl = 0; bl < 8; bl++)
                hv[bl] = *(const ulonglong2*)(hs + (bq*8 + bl)*512 + kk);
#pragma unroll
            for (int g = 0; g < 8; g++) {
                ulonglong2 wv = *(const ulonglong2*)(whh_s + (ggrp*8 + g)*512 + kk);
#pragma unroll
                for (int bl = 0; bl < 8; bl++) {
                    acc[g*8+bl] = fma2(wv.x, hv[bl].x, acc[g*8+bl]);
                    acc[g*8+bl] = fma2(wv.y, hv[bl].y, acc[g*8+bl]);
                }
            }
        }
#pragma unroll
        for (int half = 0; half < 2; half++) {
            ull* v = acc + half*32;
#pragma unroll
            for (int s = 16; s > 0; s >>= 1) {
#pragma unroll
                for (int j = 0; j < 16; j++) {
                    if (j < s) {
                        bool up_ = (lane & s) != 0;
                        ull keep = up_ ? v[j + s] : v[j];
                        ull send = up_ ? v[j]     : v[j + s];
                        ull rec = __shfl_xor_sync(0xffffffffu, send, s);
                        v[j] = add2(keep, rec);
                    }
                }
            }
        }
        {
            float2 p0 = *(float2*)&acc[0];
            float2 p1 = *(float2*)&acc[32];
            gm[r0][bcol] = p0.x + p0.y + xv0;
            gm[r1][bcol] = p1.x + p1.y + xv1;
        }
        __syncthreads();

        if (tid < 128) {
            int jj = wid, b = lane;
            float ig = gm[jj][b], fg = gm[4+jj][b], gg = gm[8+jj][b], og = gm[12+jj][b];
            float c = c_reg;
            float ct = sigf(fg)*c + sigf(ig)*tanhf(gg);
            float ht = sigf(og)*tanhf(ct);
            float ub = ubin_s[b];
            float hp = hs[b*512 + cta*4 + jj];
            float cn = ub*ct + (1.f-ub)*c;
            float hn = ub*ht + (1.f-ub)*hp;
            c_reg = cn;
            g_h[pp][b*512 + cta*4 + jj] = hn;
            if (t == TC-1) dout[(size_t)b*H_ + cta*4 + jj] = hn;
            cpart[jj][b] = cn * wuh_s[jj];
        }
        __syncthreads();
        if (tid < 32)
            g_udot[pp][cta][tid] = cpart[0][tid]+cpart[1][tid]+cpart[2][tid]+cpart[3][tid];

        // ---- flag-vector grid barrier: plain store arrival, parallel poll ----
        __syncthreads();
        if (tid == 0) {
            __threadfence();
            asm volatile("st.global.cg.u32 [%0], %1;" :: "l"(&g_arr[cta]), "r"(t + 1u) : "memory");
        }
        if (tid < 32) {
            const unsigned tgt = t + 1u;
            const unsigned* a0 = g_arr + tid*4;
            for (;;) {
                unsigned f0 = ldvol(a0+0), f1 = ldvol(a0+1);
                unsigned f2 = ldvol(a0+2), f3 = ldvol(a0+3);
                bool ok = (f0 >= tgt) & (f1 >= tgt) & (f2 >= tgt) & (f3 >= tgt);
                if (__all_sync(0xffffffffu, ok)) break;
                __nanosleep(32);
            }
            __threadfence();
        }
        __syncthreads();
    }
}

// reset barrier flags so the next graph replay starts clean
__global__ void k4_reset() { g_arr[threadIdx.x] = 0u; }

extern "C" void kernel_launch(void* const* d_in, const int* in_sizes, int n_in,
                              void* d_out, int out_size) {
    const float* x     = (const float*)d_in[0];
    const float* cw    = (const float*)d_in[1];
    const float* cb    = (const float*)d_in[2];
    const float* gamma = (const float*)d_in[3];
    const float* beta  = (const float*)d_in[4];
    const float* mean  = (const float*)d_in[5];
    const float* var   = (const float*)d_in[6];
    const float* w_ih  = (const float*)d_in[7];
    const float* w_hh  = (const float*)d_in[8];
    const float* b_ih  = (const float*)d_in[9];
    const float* b_hh  = (const float*)d_in[10];
    const float* w_uh  = (const float*)d_in[11];
    const float* b_uh  = (const float*)d_in[12];
    float* dout = (float*)d_out;

    cudaFuncSetAttribute(k2_xproj, cudaFuncAttributeMaxDynamicSharedMemorySize, 49280);
    cudaFuncSetAttribute(k3_lstm,  cudaFuncAttributeMaxDynamicSharedMemorySize, 98304);

    k0_wt<<<640, 256>>>(cw);
    k1_conv<<<dim3(2, 128), 256>>>(x, cb, gamma, beta, mean, var);
    k2_xproj<<<dim3(16, TC), 256, 49280>>>(w_ih, b_ih, b_hh);
    k3_lstm<<<NCTA3, 256, 98304>>>(w_hh, w_uh, b_uh, dout);
    k4_reset<<<1, NCTA3>>>();
}

// round 7
// speedup vs baseline: 1.5219x; 1.5219x over previous
#include <cuda_runtime.h>
#include <math.h>

#define B_    32
#define T_IN  1024
#define CIN   128
#define F_    256
#define TC    510
#define H_    512
#define G4    2048
#define M_    (TC*B_)
#define NCTA3 128

__device__ float g_wt[5*CIN*F_];
__device__ float g_y[(size_t)M_*F_];
__device__ float g_xp[(size_t)TC*G4*B_];
__device__ float g_h[2][B_*H_];
__device__ float g_udot[2][NCTA3][B_];
__device__ unsigned g_bar_cnt = 0;
__device__ unsigned g_bar_flag = 0;

typedef unsigned long long ull;

__device__ __forceinline__ ull fma2(ull a, ull b, ull c) {
    ull d;
    asm("fma.rn.f32x2 %0, %1, %2, %3;" : "=l"(d) : "l"(a), "l"(b), "l"(c));
    return d;
}
__device__ __forceinline__ ull add2(ull a, ull b) {
    ull d;
    asm("add.rn.f32x2 %0, %1, %2;" : "=l"(d) : "l"(a), "l"(b));
    return d;
}
__device__ __forceinline__ unsigned sm_u32(const void* p) {
    unsigned a;
    asm("{ .reg .u64 t; cvta.to.shared.u64 t, %1; cvt.u32.u64 %0, t; }" : "=r"(a) : "l"(p));
    return a;
}

__global__ void k0_wt(const float* __restrict__ cw) {
    int k = blockIdx.x, f = threadIdx.x;
    g_wt[(size_t)k*F_ + f] = cw[((size_t)f*CIN + (k & 127))*5 + (k >> 7)];
}

__global__ __launch_bounds__(256) void k1_conv(
    const float* __restrict__ x, const float* __restrict__ cb,
    const float* __restrict__ gamma, const float* __restrict__ beta,
    const float* __restrict__ mean, const float* __restrict__ var)
{
    __shared__ float As[16][132];
    __shared__ float Bs[16][132];
    const int n0 = blockIdx.x * 128, m0 = blockIdx.y * 128;
    const int tid = threadIdx.x, tx = tid & 15, ty = tid >> 4;
    float acc[8][8];
#pragma unroll
    for (int i = 0; i < 8; i++)
#pragma unroll
        for (int j = 0; j < 8; j++) acc[i][j] = 0.f;

    for (int ks = 0; ks < 40; ks++) {
        const int k0 = ks * 16;
#pragma unroll
        for (int i = 0; i < 2; i++) {
            int idx = tid + i*256, ml = idx >> 2, kc = (idx & 3)*4;
            int m = m0 + ml;
            float4 v = make_float4(0.f,0.f,0.f,0.f);
            if (m < M_) {
                int t = m >> 5, b = m & 31, k = k0 + kc;
                v = *(const float4*)(x + ((size_t)b*T_IN + (size_t)(2*t + (k>>7)))*CIN + (k&127));
            }
            As[kc][ml]=v.x; As[kc+1][ml]=v.y; As[kc+2][ml]=v.z; As[kc+3][ml]=v.w;
        }
#pragma unroll
        for (int i = 0; i < 2; i++) {
            int idx = tid + i*256, kr = idx >> 5, nc = (idx & 31)*4;
            float4 v = *(const float4*)(g_wt + (size_t)(k0+kr)*F_ + n0 + nc);
            Bs[kr][nc]=v.x; Bs[kr][nc+1]=v.y; Bs[kr][nc+2]=v.z; Bs[kr][nc+3]=v.w;
        }
        __syncthreads();
#pragma unroll
        for (int kk = 0; kk < 16; kk++) {
            float a[8], b[8];
            *(float4*)&a[0] = *(const float4*)&As[kk][ty*8];
            *(float4*)&a[4] = *(const float4*)&As[kk][ty*8+4];
            *(float4*)&b[0] = *(const float4*)&Bs[kk][tx*8];
            *(float4*)&b[4] = *(const float4*)&Bs[kk][tx*8+4];
#pragma unroll
            for (int i = 0; i < 8; i++)
#pragma unroll
                for (int j = 0; j < 8; j++) acc[i][j] = fmaf(a[i], b[j], acc[i][j]);
        }
        __syncthreads();
    }
    const int f0 = n0 + tx*8;
    float invs[8], adds[8], cbs[8];
#pragma unroll
    for (int j = 0; j < 8; j++) {
        float iv = gamma[f0+j] * rsqrtf(var[f0+j] + 1e-5f);
        invs[j] = iv; adds[j] = beta[f0+j] - mean[f0+j]*iv; cbs[j] = cb[f0+j];
    }
#pragma unroll
    for (int i = 0; i < 8; i++) {
        int m = m0 + ty*8 + i;
        if (m < M_) {
            float o[8];
#pragma unroll
            for (int j = 0; j < 8; j++)
                o[j] = fmaxf(acc[i][j] + cbs[j], 0.f)*invs[j] + adds[j];
            *(float4*)(g_y + (size_t)m*F_ + f0)   = make_float4(o[0],o[1],o[2],o[3]);
            *(float4*)(g_y + (size_t)m*F_ + f0+4) = make_float4(o[4],o[5],o[6],o[7]);
        }
    }
}

__global__ __launch_bounds__(256) void k2_xproj(
    const float* __restrict__ w_ih, const float* __restrict__ b_ih,
    const float* __restrict__ b_hh)
{
    extern __shared__ float sm2[];
    float* Ys = sm2;            // 32 x 257
    float* Ws = sm2 + 32*257;   // 32 x 128
    const int t = blockIdx.y, g0 = blockIdx.x * 128;
    const int tid = threadIdx.x, tx = tid & 15, ty = tid >> 4;

    const float* src = g_y + (size_t)t*32*F_;
#pragma unroll
    for (int q = 0; q < 8; q++) {
        int idx = tid + q*256, b = idx >> 6, f4 = idx & 63;
        float4 v = *(const float4*)(src + (size_t)b*F_ + f4*4);
        float* d = Ys + b*257 + f4*4;
        d[0]=v.x; d[1]=v.y; d[2]=v.z; d[3]=v.w;
    }
    float acc[8][2];
#pragma unroll
    for (int j = 0; j < 8; j++) { acc[j][0]=0.f; acc[j][1]=0.f; }

    for (int fs = 0; fs < 8; fs++) {
        __syncthreads();
#pragma unroll
        for (int q = 0; q < 4; q++) {
            int idx = tid + q*256, g = idx >> 3, f4 = idx & 7;
            float4 v = *(const float4*)(w_ih + (size_t)(g0+g)*F_ + fs*32 + f4*4);
            Ws[(f4*4  )*128+g]=v.x; Ws[(f4*4+1)*128+g]=v.y;
            Ws[(f4*4+2)*128+g]=v.z; Ws[(f4*4+3)*128+g]=v.w;
        }
        __syncthreads();
#pragma unroll
        for (int fr = 0; fr < 32; fr++) {
            float a[8];
            *(float4*)&a[0] = *(const float4*)(Ws + fr*128 + ty*8);
            *(float4*)&a[4] = *(const float4*)(Ws + fr*128 + ty*8 + 4);
            float y0 = Ys[(tx*2  )*257 + fs*32 + fr];
            float y1 = Ys[(tx*2+1)*257 + fs*32 + fr];
#pragma unroll
            for (int j = 0; j < 8; j++) {
                acc[j][0] = fmaf(a[j], y0, acc[j][0]);
                acc[j][1] = fmaf(a[j], y1, acc[j][1]);
            }
        }
    }
#pragma unroll
    for (int j = 0; j < 8; j++) {
        int g = g0 + ty*8 + j;
        float bias = b_ih[g] + b_hh[g];
        size_t base = ((size_t)t*G4 + g)*B_ + tx*2;
        g_xp[base] = acc[j][0] + bias;
        g_xp[base+1] = acc[j][1] + bias;
    }
}

__device__ __forceinline__ void grid_bar(unsigned sense) {
    __threadfence();
    __syncthreads();
    if (threadIdx.x == 0) {
        if (atomicAdd(&g_bar_cnt, 1u) == NCTA3 - 1u) {
            g_bar_cnt = 0u;
            __threadfence();
            *(volatile unsigned*)&g_bar_flag = sense;
        } else {
            while (*(volatile unsigned*)&g_bar_flag != sense) __nanosleep(64);
        }
        __threadfence();
    }
    __syncthreads();
}

__device__ __forceinline__ float sigf(float v) { return 1.f/(1.f + __expf(-v)); }

// K3: 128 CTAs x 256 thr. Bulk-async staging of h and udot; atomic grid barrier.
__global__ void __launch_bounds__(256, 1) k3_lstm(
    const float* __restrict__ w_hh, const float* __restrict__ w_uh,
    const float* __restrict__ b_uh, float* __restrict__ dout)
{
    extern __shared__ float dsm[];
    float* whh_s = dsm;             // 16 x 512   (32 KB)
    float* hs    = dsm + 8192;      // 32 x 512   (64 KB)
    float* ubuf  = dsm + 24576;     // 128 x 32   (16 KB)
    __shared__ float gm[16][33];
    __shared__ float u_s[32], ubin_s[32];
    __shared__ float4 red4[32][8];
    __shared__ float cpart[4][32];
    __shared__ float wuh_s[4];
    __shared__ __align__(8) unsigned long long mbar;

    const int cta = blockIdx.x, tid = threadIdx.x;
    const int lane = tid & 31, wid = tid >> 5;
    const unsigned mbar_a = sm_u32(&mbar);
    const unsigned hs_a   = sm_u32(hs);
    const unsigned ub_a   = sm_u32(ubuf);

    if (tid == 0)
        asm volatile("mbarrier.init.shared.b64 [%0], 1;" :: "r"(mbar_a) : "memory");

#pragma unroll
    for (int q = 0; q < 8; q++) {
        int i4 = tid + q*256;
        int r = i4 >> 7, kk = (i4 & 127)*4;
        int grow = (r >> 2)*512 + cta*4 + (r & 3);
        *(float4*)(whh_s + r*512 + kk) = *(const float4*)(w_hh + (size_t)grow*H_ + kk);
    }
    if (tid < 4) wuh_s[tid] = w_uh[cta*4 + tid];
    const float buh = b_uh[0];

    const int ggrp = wid >> 2;
    const int bq   = wid & 3;
    const int bcol = bq*8 + (lane & 7);
    const int r0 = ggrp*8 + (lane >> 3);
    const int r1 = r0 + 4;
    const int gr0 = (r0 >> 2)*512 + cta*4 + (r0 & 3);
    const int gr1 = (r1 >> 2)*512 + cta*4 + (r1 & 3);

    float c_reg = 0.f;
    unsigned sense = 1u;
    __syncthreads();

    for (int t = 0; t < TC; ++t) {
        const int pp = t & 1, pq = pp ^ 1;

        if (t > 0 && tid == 0) {
            asm volatile("fence.proxy.async;" ::: "memory");
            asm volatile("mbarrier.arrive.expect_tx.shared.b64 _, [%0], %1;"
                         :: "r"(mbar_a), "r"(81920u) : "memory");
            asm volatile("cp.async.bulk.shared::cta.global.mbarrier::complete_tx::bytes [%0], [%1], %2, [%3];"
                         :: "r"(hs_a), "l"((const void*)g_h[pq]), "r"(65536u), "r"(mbar_a) : "memory");
            asm volatile("cp.async.bulk.shared::cta.global.mbarrier::complete_tx::bytes [%0], [%1], %2, [%3];"
                         :: "r"(ub_a), "l"((const void*)&g_udot[pq][0][0]), "r"(16384u), "r"(mbar_a) : "memory");
        }

        float xv0 = __ldcg(g_xp + ((size_t)t*G4 + gr0)*B_ + bcol);
        float xv1 = __ldcg(g_xp + ((size_t)t*G4 + gr1)*B_ + bcol);

        if (t == 0) {
            float4 z = make_float4(0.f,0.f,0.f,0.f);
#pragma unroll
            for (int q = 0; q < 16; q++) *(float4*)(hs + (tid + q*256)*4) = z;
            if (tid < 32) { u_s[tid] = 1.f; ubin_s[tid] = 1.f; }
            __syncthreads();
        } else {
            // wait for bulk copies (parity = (t-1)&1)
            {
                unsigned ph = (t - 1) & 1u, done;
                asm volatile("{ .reg .pred p; mbarrier.try_wait.parity.acquire.cta.shared::cta.b64 p, [%1], %2; selp.b32 %0,1,0,p; }"
                             : "=r"(done) : "r"(mbar_a), "r"(ph) : "memory");
                while (!done) {
                    asm volatile("{ .reg .pred p; mbarrier.try_wait.parity.acquire.cta.shared::cta.b64 p, [%1], %2, 0x989680; selp.b32 %0,1,0,p; }"
                                 : "=r"(done) : "r"(mbar_a), "r"(ph) : "memory");
                }
            }
            // u-dot partial reduce from smem: thread = (ctaGroup g, b-quad)
            {
                int g = tid >> 3, b4 = tid & 7;
                const float4* up = (const float4*)ubuf;
                float4 s = up[(g*4+0)*8 + b4];
                float4 v1 = up[(g*4+1)*8 + b4];
                float4 v2 = up[(g*4+2)*8 + b4];
                float4 v3 = up[(g*4+3)*8 + b4];
                s.x += v1.x + v2.x + v3.x;
                s.y += v1.y + v2.y + v3.y;
                s.z += v1.z + v2.z + v3.z;
                s.w += v1.w + v2.w + v3.w;
                red4[g][b4] = s;
            }
            __syncthreads();
            if (tid < 32) {
                const float* rp = (const float*)red4;
                float tot = 0.f;
#pragma unroll
                for (int g2 = 0; g2 < 32; g2++) tot += rp[g2*32 + tid];
                float du = sigf(tot + buh);
                float up = u_s[tid], ub = ubin_s[tid];
                float un = ub*du + (1.f-ub)*(up + fminf(du, 1.f - up));
                u_s[tid] = un; ubin_s[tid] = rintf(un);
            }
        }

        ull acc[64];
#pragma unroll
        for (int j = 0; j < 64; j++) acc[j] = 0ULL;
#pragma unroll
        for (int i = 0; i < 4; i++) {
            const int kk = 4*lane + 128*i;
            ulonglong2 hv[8];
#pragma unroll
            for (int bl = 0; bl < 8; bl++)
                hv[bl] = *(const ulonglong2*)(hs + (bq*8 + bl)*512 + kk);
#pragma unroll
            for (int g = 0; g < 8; g++) {
                ulonglong2 wv = *(const ulonglong2*)(whh_s + (ggrp*8 + g)*512 + kk);
#pragma unroll
                for (int bl = 0; bl < 8; bl++) {
                    acc[g*8+bl] = fma2(wv.x, hv[bl].x, acc[g*8+bl]);
                    acc[g*8+bl] = fma2(wv.y, hv[bl].y, acc[g*8+bl]);
                }
            }
        }
#pragma unroll
        for (int half = 0; half < 2; half++) {
            ull* v = acc + half*32;
#pragma unroll
            for (int s = 16; s > 0; s >>= 1) {
#pragma unroll
                for (int j = 0; j < 16; j++) {
                    if (j < s) {
                        bool up_ = (lane & s) != 0;
                        ull keep = up_ ? v[j + s] : v[j];
                        ull send = up_ ? v[j]     : v[j + s];
                        ull rec = __shfl_xor_sync(0xffffffffu, send, s);
                        v[j] = add2(keep, rec);
                    }
                }
            }
        }
        {
            float2 p0 = *(float2*)&acc[0];
            float2 p1 = *(float2*)&acc[32];
            gm[r0][bcol] = p0.x + p0.y + xv0;
            gm[r1][bcol] = p1.x + p1.y + xv1;
        }
        __syncthreads();

        if (tid < 128) {
            int jj = wid, b = lane;
            float ig = gm[jj][b], fg = gm[4+jj][b], gg = gm[8+jj][b], og = gm[12+jj][b];
            float c = c_reg;
            float ct = sigf(fg)*c + sigf(ig)*tanhf(gg);
            float ht = sigf(og)*tanhf(ct);
            float ub = ubin_s[b];
            float hp = hs[b*512 + cta*4 + jj];
            float cn = ub*ct + (1.f-ub)*c;
            float hn = ub*ht + (1.f-ub)*hp;
            c_reg = cn;
            g_h[pp][b*512 + cta*4 + jj] = hn;
            if (t == TC-1) dout[(size_t)b*H_ + cta*4 + jj] = hn;
            cpart[jj][b] = cn * wuh_s[jj];
        }
        __syncthreads();
        if (tid < 32)
            g_udot[pp][cta][tid] = cpart[0][tid]+cpart[1][tid]+cpart[2][tid]+cpart[3][tid];

        grid_bar(sense);
        sense ^= 1u;
    }
}

extern "C" void kernel_launch(void* const* d_in, const int* in_sizes, int n_in,
                              void* d_out, int out_size) {
    const float* x     = (const float*)d_in[0];
    const float* cw    = (const float*)d_in[1];
    const float* cb    = (const float*)d_in[2];
    const float* gamma = (const float*)d_in[3];
    const float* beta  = (const float*)d_in[4];
    const float* mean  = (const float*)d_in[5];
    const float* var   = (const float*)d_in[6];
    const float* w_ih  = (const float*)d_in[7];
    const float* w_hh  = (const float*)d_in[8];
    const float* b_ih  = (const float*)d_in[9];
    const float* b_hh  = (const float*)d_in[10];
    const float* w_uh  = (const float*)d_in[11];
    const float* b_uh  = (const float*)d_in[12];
    float* dout = (float*)d_out;

    cudaFuncSetAttribute(k2_xproj, cudaFuncAttributeMaxDynamicSharedMemorySize, 49280);
    cudaFuncSetAttribute(k3_lstm,  cudaFuncAttributeMaxDynamicSharedMemorySize, 114688);

    k0_wt<<<640, 256>>>(cw);
    k1_conv<<<dim3(2, 128), 256>>>(x, cb, gamma, beta, mean, var);
    k2_xproj<<<dim3(16, TC), 256, 49280>>>(w_ih, b_ih, b_hh);
    k3_lstm<<<NCTA3, 256, 114688>>>(w_hh, w_uh, b_uh, dout);
}

// round 9
// speedup vs baseline: 1.5318x; 1.0065x over previous
#include <cuda_runtime.h>
#include <math.h>

#define B_    32
#define T_IN  1024
#define CIN   128
#define F_    256
#define TC    510
#define H_    512
#define G4    2048
#define M_    (TC*B_)
#define NCTA3 128

__device__ float g_wt[5*CIN*F_];
__device__ float g_y[(size_t)M_*F_];
__device__ float g_xp[(size_t)TC*G4*B_];
__device__ float g_h[2][B_*H_];
__device__ float g_udot[2][NCTA3][B_];
__device__ unsigned g_bar_cnt = 0;
__device__ unsigned g_bar_flag = 0;

typedef unsigned long long ull;

__device__ __forceinline__ ull fma2(ull a, ull b, ull c) {
    ull d;
    asm("fma.rn.f32x2 %0, %1, %2, %3;" : "=l"(d) : "l"(a), "l"(b), "l"(c));
    return d;
}
__device__ __forceinline__ ull add2(ull a, ull b) {
    ull d;
    asm("add.rn.f32x2 %0, %1, %2;" : "=l"(d) : "l"(a), "l"(b));
    return d;
}
__device__ __forceinline__ ull pack2(float lo, float hi) {
    ull d;
    asm("mov.b64 %0, {%1, %2};" : "=l"(d) : "f"(lo), "f"(hi));
    return d;
}
__device__ __forceinline__ float2 unpack2(ull v) {
    float2 r;
    asm("mov.b64 {%0, %1}, %2;" : "=f"(r.x), "=f"(r.y) : "l"(v));
    return r;
}
__device__ __forceinline__ unsigned sm_u32(const void* p) {
    unsigned a;
    asm("{ .reg .u64 t; cvta.to.shared.u64 t, %1; cvt.u32.u64 %0, t; }" : "=r"(a) : "l"(p));
    return a;
}

__global__ void k0_wt(const float* __restrict__ cw) {
    int k = blockIdx.x, f = threadIdx.x;
    g_wt[(size_t)k*F_ + f] = cw[((size_t)f*CIN + (k & 127))*5 + (k >> 7)];
}

// K1: conv+relu+bn GEMM, f32x2 inner product (j-pairs packed)
__global__ __launch_bounds__(256) void k1_conv(
    const float* __restrict__ x, const float* __restrict__ cb,
    const float* __restrict__ gamma, const float* __restrict__ beta,
    const float* __restrict__ mean, const float* __restrict__ var)
{
    __shared__ float As[16][132];
    __shared__ float Bs[16][132];
    const int n0 = blockIdx.x * 128, m0 = blockIdx.y * 128;
    const int tid = threadIdx.x, tx = tid & 15, ty = tid >> 4;
    ull acc2[8][4];
#pragma unroll
    for (int i = 0; i < 8; i++)
#pragma unroll
        for (int j = 0; j < 4; j++) acc2[i][j] = 0ULL;

    for (int ks = 0; ks < 40; ks++) {
        const int k0 = ks * 16;
#pragma unroll
        for (int i = 0; i < 2; i++) {
            int idx = tid + i*256, ml = idx >> 2, kc = (idx & 3)*4;
            int m = m0 + ml;
            float4 v = make_float4(0.f,0.f,0.f,0.f);
            if (m < M_) {
                int t = m >> 5, b = m & 31, k = k0 + kc;
                v = *(const float4*)(x + ((size_t)b*T_IN + (size_t)(2*t + (k>>7)))*CIN + (k&127));
            }
            As[kc][ml]=v.x; As[kc+1][ml]=v.y; As[kc+2][ml]=v.z; As[kc+3][ml]=v.w;
        }
#pragma unroll
        for (int i = 0; i < 2; i++) {
            int idx = tid + i*256, kr = idx >> 5, nc = (idx & 31)*4;
            float4 v = *(const float4*)(g_wt + (size_t)(k0+kr)*F_ + n0 + nc);
            Bs[kr][nc]=v.x; Bs[kr][nc+1]=v.y; Bs[kr][nc+2]=v.z; Bs[kr][nc+3]=v.w;
        }
        __syncthreads();
#pragma unroll
        for (int kk = 0; kk < 16; kk++) {
            float a[8];
            *(float4*)&a[0] = *(const float4*)&As[kk][ty*8];
            *(float4*)&a[4] = *(const float4*)&As[kk][ty*8+4];
            ulonglong2 bL = *(const ulonglong2*)&Bs[kk][tx*8];
            ulonglong2 bH = *(const ulonglong2*)&Bs[kk][tx*8+4];
#pragma unroll
            for (int i = 0; i < 8; i++) {
                ull ai = pack2(a[i], a[i]);
                acc2[i][0] = fma2(ai, bL.x, acc2[i][0]);
                acc2[i][1] = fma2(ai, bL.y, acc2[i][1]);
                acc2[i][2] = fma2(ai, bH.x, acc2[i][2]);
                acc2[i][3] = fma2(ai, bH.y, acc2[i][3]);
            }
        }
        __syncthreads();
    }
    const int f0 = n0 + tx*8;
    float invs[8], adds[8], cbs[8];
#pragma unroll
    for (int j = 0; j < 8; j++) {
        float iv = gamma[f0+j] * rsqrtf(var[f0+j] + 1e-5f);
        invs[j] = iv; adds[j] = beta[f0+j] - mean[f0+j]*iv; cbs[j] = cb[f0+j];
    }
#pragma unroll
    for (int i = 0; i < 8; i++) {
        int m = m0 + ty*8 + i;
        if (m < M_) {
            float o[8];
#pragma unroll
            for (int j2 = 0; j2 < 4; j2++) {
                float2 p = unpack2(acc2[i][j2]);
                o[j2*2]   = fmaxf(p.x + cbs[j2*2],   0.f)*invs[j2*2]   + adds[j2*2];
                o[j2*2+1] = fmaxf(p.y + cbs[j2*2+1], 0.f)*invs[j2*2+1] + adds[j2*2+1];
            }
            *(float4*)(g_y + (size_t)m*F_ + f0)   = make_float4(o[0],o[1],o[2],o[3]);
            *(float4*)(g_y + (size_t)m*F_ + f0+4) = make_float4(o[4],o[5],o[6],o[7]);
        }
    }
}

// K2: x_proj GEMM, f32x2 (gate-pairs packed; y duplicated)
__global__ __launch_bounds__(256) void k2_xproj(
    const float* __restrict__ w_ih, const float* __restrict__ b_ih,
    const float* __restrict__ b_hh)
{
    extern __shared__ float sm2[];
    float* Ys = sm2;            // 32 x 257
    float* Ws = sm2 + 32*257;   // 32 x 128
    const int t = blockIdx.y, g0 = blockIdx.x * 128;
    const int tid = threadIdx.x, tx = tid & 15, ty = tid >> 4;

    const float* src = g_y + (size_t)t*32*F_;
#pragma unroll
    for (int q = 0; q < 8; q++) {
        int idx = tid + q*256, b = idx >> 6, f4 = idx & 63;
        float4 v = *(const float4*)(src + (size_t)b*F_ + f4*4);
        float* d = Ys + b*257 + f4*4;
        d[0]=v.x; d[1]=v.y; d[2]=v.z; d[3]=v.w;
    }
    ull acc2[4][2];
#pragma unroll
    for (int j = 0; j < 4; j++) { acc2[j][0]=0ULL; acc2[j][1]=0ULL; }

    for (int fs = 0; fs < 8; fs++) {
        __syncthreads();
#pragma unroll
        for (int q = 0; q < 4; q++) {
            int idx = tid + q*256, g = idx >> 3, f4 = idx & 7;
            float4 v = *(const float4*)(w_ih + (size_t)(g0+g)*F_ + fs*32 + f4*4);
            Ws[(f4*4  )*128+g]=v.x; Ws[(f4*4+1)*128+g]=v.y;
            Ws[(f4*4+2)*128+g]=v.z; Ws[(f4*4+3)*128+g]=v.w;
        }
        __syncthreads();
#pragma unroll
        for (int fr = 0; fr < 32; fr++) {
            ulonglong2 aL = *(const ulonglong2*)(Ws + fr*128 + ty*8);
            ulonglong2 aH = *(const ulonglong2*)(Ws + fr*128 + ty*8 + 4);
            float y0 = Ys[(tx*2  )*257 + fs*32 + fr];
            float y1 = Ys[(tx*2+1)*257 + fs*32 + fr];
            ull y00 = pack2(y0, y0);
            ull y11 = pack2(y1, y1);
            acc2[0][0] = fma2(aL.x, y00, acc2[0][0]);
            acc2[1][0] = fma2(aL.y, y00, acc2[1][0]);
            acc2[2][0] = fma2(aH.x, y00, acc2[2][0]);
            acc2[3][0] = fma2(aH.y, y00, acc2[3][0]);
            acc2[0][1] = fma2(aL.x, y11, acc2[0][1]);
            acc2[1][1] = fma2(aL.y, y11, acc2[1][1]);
            acc2[2][1] = fma2(aH.x, y11, acc2[2][1]);
            acc2[3][1] = fma2(aH.y, y11, acc2[3][1]);
        }
    }
#pragma unroll
    for (int j2 = 0; j2 < 4; j2++) {
        int g = g0 + ty*8 + j2*2;
        float bias0 = b_ih[g]   + b_hh[g];
        float bias1 = b_ih[g+1] + b_hh[g+1];
        float2 p0 = unpack2(acc2[j2][0]);   // gates g,g+1 for batch tx*2
        float2 p1 = unpack2(acc2[j2][1]);   // gates g,g+1 for batch tx*2+1
        size_t base0 = ((size_t)t*G4 + g  )*B_ + tx*2;
        size_t base1 = ((size_t)t*G4 + g+1)*B_ + tx*2;
        g_xp[base0]   = p0.x + bias0;
        g_xp[base0+1] = p1.x + bias0;
        g_xp[base1]   = p0.y + bias1;
        g_xp[base1+1] = p1.y + bias1;
    }
}

__device__ __forceinline__ void grid_bar(unsigned sense) {
    __threadfence();
    __syncthreads();
    if (threadIdx.x == 0) {
        if (atomicAdd(&g_bar_cnt, 1u) == NCTA3 - 1u) {
            g_bar_cnt = 0u;
            __threadfence();
            *(volatile unsigned*)&g_bar_flag = sense;
        } else {
            while (*(volatile unsigned*)&g_bar_flag != sense) __nanosleep(64);
        }
        __threadfence();
    }
    __syncthreads();
}

__device__ __forceinline__ float sigf(float v) { return 1.f/(1.f + __expf(-v)); }

// K3: 128 CTAs x 256 thr. Bulk-async staging of h and udot; atomic grid barrier.
__global__ void __launch_bounds__(256, 1) k3_lstm(
    const float* __restrict__ w_hh, const float* __restrict__ w_uh,
    const float* __restrict__ b_uh, float* __restrict__ dout)
{
    extern __shared__ float dsm[];
    float* whh_s = dsm;             // 16 x 512   (32 KB)
    float* hs    = dsm + 8192;      // 32 x 512   (64 KB)
    float* ubuf  = dsm + 24576;     // 128 x 32   (16 KB)
    __shared__ float gm[16][33];
    __shared__ float u_s[32], ubin_s[32];
    __shared__ float4 red4[32][8];
    __shared__ float cpart[4][32];
    __shared__ float wuh_s[4];
    __shared__ __align__(8) unsigned long long mbar;

    const int cta = blockIdx.x, tid = threadIdx.x;
    const int lane = tid & 31, wid = tid >> 5;
    const unsigned mbar_a = sm_u32(&mbar);
    const unsigned hs_a   = sm_u32(hs);
    const unsigned ub_a   = sm_u32(ubuf);

    if (tid == 0)
        asm volatile("mbarrier.init.shared.b64 [%0], 1;" :: "r"(mbar_a) : "memory");

#pragma unroll
    for (int q = 0; q < 8; q++) {
        int i4 = tid + q*256;
        int r = i4 >> 7, kk = (i4 & 127)*4;
        int grow = (r >> 2)*512 + cta*4 + (r & 3);
        *(float4*)(whh_s + r*512 + kk) = *(const float4*)(w_hh + (size_t)grow*H_ + kk);
    }
    if (tid < 4) wuh_s[tid] = w_uh[cta*4 + tid];
    const float buh = b_uh[0];

    const int ggrp = wid >> 2;
    const int bq   = wid & 3;
    const int bcol = bq*8 + (lane & 7);
    const int r0 = ggrp*8 + (lane >> 3);
    const int r1 = r0 + 4;
    const int gr0 = (r0 >> 2)*512 + cta*4 + (r0 & 3);
    const int gr1 = (r1 >> 2)*512 + cta*4 + (r1 & 3);

    float c_reg = 0.f;
    unsigned sense = 1u;
    __syncthreads();

    for (int t = 0; t < TC; ++t) {
        const int pp = t & 1, pq = pp ^ 1;

        if (t > 0 && tid == 0) {
            asm volatile("fence.proxy.async;" ::: "memory");
            asm volatile("mbarrier.arrive.expect_tx.shared.b64 _, [%0], %1;"
                         :: "r"(mbar_a), "r"(81920u) : "memory");
            asm volatile("cp.async.bulk.shared::cta.global.mbarrier::complete_tx::bytes [%0], [%1], %2, [%3];"
                         :: "r"(hs_a), "l"((const void*)g_h[pq]), "r"(65536u), "r"(mbar_a) : "memory");
            asm volatile("cp.async.bulk.shared::cta.global.mbarrier::complete_tx::bytes [%0], [%1], %2, [%3];"
                         :: "r"(ub_a), "l"((const void*)&g_udot[pq][0][0]), "r"(16384u), "r"(mbar_a) : "memory");
        }

        float xv0 = __ldcg(g_xp + ((size_t)t*G4 + gr0)*B_ + bcol);
        float xv1 = __ldcg(g_xp + ((size_t)t*G4 + gr1)*B_ + bcol);

        if (t == 0) {
            float4 z = make_float4(0.f,0.f,0.f,0.f);
#pragma unroll
            for (int q = 0; q < 16; q++) *(float4*)(hs + (tid + q*256)*4) = z;
            if (tid < 32) { u_s[tid] = 1.f; ubin_s[tid] = 1.f; }
            __syncthreads();
        } else {
            {
                unsigned ph = (t - 1) & 1u, done;
                asm volatile("{ .reg .pred p; mbarrier.try_wait.parity.acquire.cta.shared::cta.b64 p, [%1], %2; selp.b32 %0,1,0,p; }"
                             : "=r"(done) : "r"(mbar_a), "r"(ph) : "memory");
                while (!done) {
                    asm volatile("{ .reg .pred p; mbarrier.try_wait.parity.acquire.cta.shared::cta.b64 p, [%1], %2, 0x989680; selp.b32 %0,1,0,p; }"
                                 : "=r"(done) : "r"(mbar_a), "r"(ph) : "memory");
                }
            }
            {
                int g = tid >> 3, b4 = tid & 7;
                const float4* up = (const float4*)ubuf;
                float4 s = up[(g*4+0)*8 + b4];
                float4 v1 = up[(g*4+1)*8 + b4];
                float4 v2 = up[(g*4+2)*8 + b4];
                float4 v3 = up[(g*4+3)*8 + b4];
                s.x += v1.x + v2.x + v3.x;
                s.y += v1.y + v2.y + v3.y;
                s.z += v1.z + v2.z + v3.z;
                s.w += v1.w + v2.w + v3.w;
                red4[g][b4] = s;
            }
            __syncthreads();
            if (tid < 32) {
                const float* rp = (const float*)red4;
                float tot = 0.f;
#pragma unroll
                for (int g2 = 0; g2 < 32; g2++) tot += rp[g2*32 + tid];
                float du = sigf(tot + buh);
                float up = u_s[tid], ub = ubin_s[tid];
                float un = ub*du + (1.f-ub)*(up + fminf(du, 1.f - up));
                u_s[tid] = un; ubin_s[tid] = rintf(un);
            }
        }

        ull acc[64];
#pragma unroll
        for (int j = 0; j < 64; j++) acc[j] = 0ULL;
#pragma unroll
        for (int i = 0; i < 4; i++) {
            const int kk = 4*lane + 128*i;
            ulonglong2 hv[8];
#pragma unroll
            for (int bl = 0; bl < 8; bl++)
                hv[bl] = *(const ulonglong2*)(hs + (bq*8 + bl)*512 + kk);
#pragma unroll
            for (int g = 0; g < 8; g++) {
                ulonglong2 wv = *(const ulonglong2*)(whh_s + (ggrp*8 + g)*512 + kk);
#pragma unroll
                for (int bl = 0; bl < 8; bl++) {
                    acc[g*8+bl] = fma2(wv.x, hv[bl].x, acc[g*8+bl]);
                    acc[g*8+bl] = fma2(wv.y, hv[bl].y, acc[g*8+bl]);
                }
            }
        }
#pragma unroll
        for (int half = 0; half < 2; half++) {
            ull* v = acc + half*32;
#pragma unroll
            for (int s = 16; s > 0; s >>= 1) {
#pragma unroll
                for (int j = 0; j < 16; j++) {
                    if (j < s) {
                        bool up_ = (lane & s) != 0;
                        ull keep = up_ ? v[j + s] : v[j];
                        ull send = up_ ? v[j]     : v[j + s];
                        ull rec = __shfl_xor_sync(0xffffffffu, send, s);
                        v[j] = add2(keep, rec);
                    }
                }
            }
        }
        {
            float2 p0 = unpack2(acc[0]);
            float2 p1 = unpack2(acc[32]);
            gm[r0][bcol] = p0.x + p0.y + xv0;
            gm[r1][bcol] = p1.x + p1.y + xv1;
        }
        __syncthreads();

        if (tid < 128) {
            int jj = wid, b = lane;
            float ig = gm[jj][b], fg = gm[4+jj][b], gg = gm[8+jj][b], og = gm[12+jj][b];
            float c = c_reg;
            float ct = sigf(fg)*c + sigf(ig)*tanhf(gg);
            float ht = sigf(og)*tanhf(ct);
            float ub = ubin_s[b];
            float hp = hs[b*512 + cta*4 + jj];
            float cn = ub*ct + (1.f-ub)*c;
            float hn = ub*ht + (1.f-ub)*hp;
            c_reg = cn;
            g_h[pp][b*512 + cta*4 + jj] = hn;
            if (t == TC-1) dout[(size_t)b*H_ + cta*4 + jj] = hn;
            cpart[jj][b] = cn * wuh_s[jj];
        }
        __syncthreads();
        if (tid < 32)
            g_udot[pp][cta][tid] = cpart[0][tid]+cpart[1][tid]+cpart[2][tid]+cpart[3][tid];

        grid_bar(sense);
        sense ^= 1u;
    }
}

extern "C" void kernel_launch(void* const* d_in, const int* in_sizes, int n_in,
                              void* d_out, int out_size) {
    const float* x     = (const float*)d_in[0];
    const float* cw    = (const float*)d_in[1];
    const float* cb    = (const float*)d_in[2];
    const float* gamma = (const float*)d_in[3];
    const float* beta  = (const float*)d_in[4];
    const float* mean  = (const float*)d_in[5];
    const float* var   = (const float*)d_in[6];
    const float* w_ih  = (const float*)d_in[7];
    const float* w_hh  = (const float*)d_in[8];
    const float* b_ih  = (const float*)d_in[9];
    const float* b_hh  = (const float*)d_in[10];
    const float* w_uh  = (const float*)d_in[11];
    const float* b_uh  = (const float*)d_in[12];
    float* dout = (float*)d_out;

    cudaFuncSetAttribute(k2_xproj, cudaFuncAttributeMaxDynamicSharedMemorySize, 49280);
    cudaFuncSetAttribute(k3_lstm,  cudaFuncAttributeMaxDynamicSharedMemorySize, 114688);

    k0_wt<<<640, 256>>>(cw);
    k1_conv<<<dim3(2, 128), 256>>>(x, cb, gamma, beta, mean, var);
    k2_xproj<<<dim3(16, TC), 256, 49280>>>(w_ih, b_ih, b_hh);
    k3_lstm<<<NCTA3, 256, 114688>>>(w_hh, w_uh, b_uh, dout);
}

// round 10
// speedup vs baseline: 1.5545x; 1.0148x over previous
#include <cuda_runtime.h>
#include <math.h>

#define B_    32
#define T_IN  1024
#define CIN   128
#define F_    256
#define TC    510
#define H_    512
#define G4    2048
#define M_    (TC*B_)
#define NCTA3 128

__device__ float g_wt[5*CIN*F_];
__device__ float g_y[(size_t)M_*F_];
__device__ float g_xp[(size_t)TC*G4*B_];
__device__ float g_h[2][B_*H_];
__device__ float g_uacc[4][32*32];     // line-padded: slot b at [phase][b*32]
__device__ unsigned g_bar_cnt = 0;
__device__ unsigned g_bar_flag = 0;

typedef unsigned long long ull;

__device__ __forceinline__ ull fma2(ull a, ull b, ull c) {
    ull d;
    asm("fma.rn.f32x2 %0, %1, %2, %3;" : "=l"(d) : "l"(a), "l"(b), "l"(c));
    return d;
}
__device__ __forceinline__ ull add2(ull a, ull b) {
    ull d;
    asm("add.rn.f32x2 %0, %1, %2;" : "=l"(d) : "l"(a), "l"(b));
    return d;
}
__device__ __forceinline__ ull pack2(float lo, float hi) {
    ull d;
    asm("mov.b64 %0, {%1, %2};" : "=l"(d) : "f"(lo), "f"(hi));
    return d;
}
__device__ __forceinline__ float2 unpack2(ull v) {
    float2 r;
    asm("mov.b64 {%0, %1}, %2;" : "=f"(r.x), "=f"(r.y) : "l"(v));
    return r;
}

__global__ void k0_wt(const float* __restrict__ cw) {
    int k = blockIdx.x, f = threadIdx.x;
    g_wt[(size_t)k*F_ + f] = cw[((size_t)f*CIN + (k & 127))*5 + (k >> 7)];
}

__global__ __launch_bounds__(256) void k1_conv(
    const float* __restrict__ x, const float* __restrict__ cb,
    const float* __restrict__ gamma, const float* __restrict__ beta,
    const float* __restrict__ mean, const float* __restrict__ var)
{
    __shared__ float As[16][132];
    __shared__ float Bs[16][132];
    const int n0 = blockIdx.x * 128, m0 = blockIdx.y * 128;
    const int tid = threadIdx.x, tx = tid & 15, ty = tid >> 4;
    ull acc2[8][4];
#pragma unroll
    for (int i = 0; i < 8; i++)
#pragma unroll
        for (int j = 0; j < 4; j++) acc2[i][j] = 0ULL;

    for (int ks = 0; ks < 40; ks++) {
        const int k0 = ks * 16;
#pragma unroll
        for (int i = 0; i < 2; i++) {
            int idx = tid + i*256, ml = idx >> 2, kc = (idx & 3)*4;
            int m = m0 + ml;
            float4 v = make_float4(0.f,0.f,0.f,0.f);
            if (m < M_) {
                int t = m >> 5, b = m & 31, k = k0 + kc;
                v = *(const float4*)(x + ((size_t)b*T_IN + (size_t)(2*t + (k>>7)))*CIN + (k&127));
            }
            As[kc][ml]=v.x; As[kc+1][ml]=v.y; As[kc+2][ml]=v.z; As[kc+3][ml]=v.w;
        }
#pragma unroll
        for (int i = 0; i < 2; i++) {
            int idx = tid + i*256, kr = idx >> 5, nc = (idx & 31)*4;
            float4 v = *(const float4*)(g_wt + (size_t)(k0+kr)*F_ + n0 + nc);
            Bs[kr][nc]=v.x; Bs[kr][nc+1]=v.y; Bs[kr][nc+2]=v.z; Bs[kr][nc+3]=v.w;
        }
        __syncthreads();
#pragma unroll
        for (int kk = 0; kk < 16; kk++) {
            float a[8];
            *(float4*)&a[0] = *(const float4*)&As[kk][ty*8];
            *(float4*)&a[4] = *(const float4*)&As[kk][ty*8+4];
            ulonglong2 bL = *(const ulonglong2*)&Bs[kk][tx*8];
            ulonglong2 bH = *(const ulonglong2*)&Bs[kk][tx*8+4];
#pragma unroll
            for (int i = 0; i < 8; i++) {
                ull ai = pack2(a[i], a[i]);
                acc2[i][0] = fma2(ai, bL.x, acc2[i][0]);
                acc2[i][1] = fma2(ai, bL.y, acc2[i][1]);
                acc2[i][2] = fma2(ai, bH.x, acc2[i][2]);
                acc2[i][3] = fma2(ai, bH.y, acc2[i][3]);
            }
        }
        __syncthreads();
    }
    const int f0 = n0 + tx*8;
    float invs[8], adds[8], cbs[8];
#pragma unroll
    for (int j = 0; j < 8; j++) {
        float iv = gamma[f0+j] * rsqrtf(var[f0+j] + 1e-5f);
        invs[j] = iv; adds[j] = beta[f0+j] - mean[f0+j]*iv; cbs[j] = cb[f0+j];
    }
#pragma unroll
    for (int i = 0; i < 8; i++) {
        int m = m0 + ty*8 + i;
        if (m < M_) {
            float o[8];
#pragma unroll
            for (int j2 = 0; j2 < 4; j2++) {
                float2 p = unpack2(acc2[i][j2]);
                o[j2*2]   = fmaxf(p.x + cbs[j2*2],   0.f)*invs[j2*2]   + adds[j2*2];
                o[j2*2+1] = fmaxf(p.y + cbs[j2*2+1], 0.f)*invs[j2*2+1] + adds[j2*2+1];
            }
            *(float4*)(g_y + (size_t)m*F_ + f0)   = make_float4(o[0],o[1],o[2],o[3]);
            *(float4*)(g_y + (size_t)m*F_ + f0+4) = make_float4(o[4],o[5],o[6],o[7]);
        }
    }
}

__global__ __launch_bounds__(256) void k2_xproj(
    const float* __restrict__ w_ih, const float* __restrict__ b_ih,
    const float* __restrict__ b_hh)
{
    extern __shared__ float sm2[];
    float* Ys = sm2;            // 32 x 257
    float* Ws = sm2 + 32*257;   // 32 x 128
    const int t = blockIdx.y, g0 = blockIdx.x * 128;
    const int tid = threadIdx.x, tx = tid & 15, ty = tid >> 4;

    const float* src = g_y + (size_t)t*32*F_;
#pragma unroll
    for (int q = 0; q < 8; q++) {
        int idx = tid + q*256, b = idx >> 6, f4 = idx & 63;
        float4 v = *(const float4*)(src + (size_t)b*F_ + f4*4);
        float* d = Ys + b*257 + f4*4;
        d[0]=v.x; d[1]=v.y; d[2]=v.z; d[3]=v.w;
    }
    ull acc2[4][2];
#pragma unroll
    for (int j = 0; j < 4; j++) { acc2[j][0]=0ULL; acc2[j][1]=0ULL; }

    for (int fs = 0; fs < 8; fs++) {
        __syncthreads();
#pragma unroll
        for (int q = 0; q < 4; q++) {
            int idx = tid + q*256, g = idx >> 3, f4 = idx & 7;
            float4 v = *(const float4*)(w_ih + (size_t)(g0+g)*F_ + fs*32 + f4*4);
            Ws[(f4*4  )*128+g]=v.x; Ws[(f4*4+1)*128+g]=v.y;
            Ws[(f4*4+2)*128+g]=v.z; Ws[(f4*4+3)*128+g]=v.w;
        }
        __syncthreads();
#pragma unroll
        for (int fr = 0; fr < 32; fr++) {
            ulonglong2 aL = *(const ulonglong2*)(Ws + fr*128 + ty*8);
            ulonglong2 aH = *(const ulonglong2*)(Ws + fr*128 + ty*8 + 4);
            float y0 = Ys[(tx*2  )*257 + fs*32 + fr];
            float y1 = Ys[(tx*2+1)*257 + fs*32 + fr];
            ull y00 = pack2(y0, y0);
            ull y11 = pack2(y1, y1);
            acc2[0][0] = fma2(aL.x, y00, acc2[0][0]);
            acc2[1][0] = fma2(aL.y, y00, acc2[1][0]);
            acc2[2][0] = fma2(aH.x, y00, acc2[2][0]);
            acc2[3][0] = fma2(aH.y, y00, acc2[3][0]);
            acc2[0][1] = fma2(aL.x, y11, acc2[0][1]);
            acc2[1][1] = fma2(aL.y, y11, acc2[1][1]);
            acc2[2][1] = fma2(aH.x, y11, acc2[2][1]);
            acc2[3][1] = fma2(aH.y, y11, acc2[3][1]);
        }
    }
#pragma unroll
    for (int j2 = 0; j2 < 4; j2++) {
        int g = g0 + ty*8 + j2*2;
        float bias0 = b_ih[g]   + b_hh[g];
        float bias1 = b_ih[g+1] + b_hh[g+1];
        float2 p0 = unpack2(acc2[j2][0]);
        float2 p1 = unpack2(acc2[j2][1]);
        size_t base0 = ((size_t)t*G4 + g  )*B_ + tx*2;
        size_t base1 = ((size_t)t*G4 + g+1)*B_ + tx*2;
        g_xp[base0]   = p0.x + bias0;
        g_xp[base0+1] = p1.x + bias0;
        g_xp[base1]   = p0.y + bias1;
        g_xp[base1+1] = p1.y + bias1;
    }
}

__device__ __forceinline__ void grid_bar(unsigned sense) {
    __threadfence();
    __syncthreads();
    if (threadIdx.x == 0) {
        if (atomicAdd(&g_bar_cnt, 1u) == NCTA3 - 1u) {
            g_bar_cnt = 0u;
            __threadfence();
            *(volatile unsigned*)&g_bar_flag = sense;
        } else {
            while (*(volatile unsigned*)&g_bar_flag != sense) __nanosleep(64);
        }
        __threadfence();
    }
    __syncthreads();
}

__device__ __forceinline__ float sigf(float v) { return 1.f/(1.f + __expf(-v)); }

// K3: 128 CTAs x 256 thr. Direct-from-L2 matvec (.cg), REDG u-dot, no staging.
__global__ void __launch_bounds__(256, 1) k3_lstm(
    const float* __restrict__ w_hh, const float* __restrict__ w_uh,
    const float* __restrict__ b_uh, float* __restrict__ dout)
{
    extern __shared__ float dsm[];
    float* whh_s = dsm;             // 16 x 512 (32 KB)
    __shared__ float gm[16][33];
    __shared__ float u_s[32], ubin_s[32];
    __shared__ float cpart[4][32];
    __shared__ float wuh_s[4];

    const int cta = blockIdx.x, tid = threadIdx.x;
    const int lane = tid & 31, wid = tid >> 5;

#pragma unroll
    for (int q = 0; q < 8; q++) {
        int i4 = tid + q*256;
        int r = i4 >> 7, kk = (i4 & 127)*4;
        int grow = (r >> 2)*512 + cta*4 + (r & 3);
        *(float4*)(whh_s + r*512 + kk) = *(const float4*)(w_hh + (size_t)grow*H_ + kk);
    }
    if (tid < 4) wuh_s[tid] = w_uh[cta*4 + tid];
    const float buh = b_uh[0];

    const int ggrp = wid >> 2;
    const int bq   = wid & 3;
    const int bcol = bq*8 + (lane & 7);
    const int r0 = ggrp*8 + (lane >> 3);
    const int r1 = r0 + 4;
    const int gr0 = (r0 >> 2)*512 + cta*4 + (r0 & 3);
    const int gr1 = (r1 >> 2)*512 + cta*4 + (r1 & 3);

    float c_reg = 0.f;
    unsigned sense = 1u;
    __syncthreads();

    for (int t = 0; t < TC; ++t) {
        const int pp = t & 1, pq = pp ^ 1;
        const float* hsrc = g_h[pq];

        // early prefetches (no deps)
        float xv0 = __ldcg(g_xp + ((size_t)t*G4 + gr0)*B_ + bcol);
        float xv1 = __ldcg(g_xp + ((size_t)t*G4 + gr1)*B_ + bcol);
        float hp = 0.f;
        if (t > 0 && tid < 128) hp = __ldcg(hsrc + lane*512 + cta*4 + wid);

        // u-chain (warp 0) + buffer zeroing (cta 0, warp 1)
        if (t > 0) {
            if (wid == 0) {
                float tot = __ldcg(&g_uacc[t & 3][lane*32]);
                float du = sigf(tot + buh);
                float up = u_s[lane], ub = ubin_s[lane];
                float un = ub*du + (1.f-ub)*(up + fminf(du, 1.f - up));
                u_s[lane] = un; ubin_s[lane] = rintf(un);
            }
        } else if (wid == 0) { u_s[lane] = 1.f; ubin_s[lane] = 1.f; }
        if (cta == 0 && wid == 1) g_uacc[(t + 2) & 3][lane*32] = 0.f;

        // matvec: h straight from L2
        ull acc[64];
#pragma unroll
        for (int j = 0; j < 64; j++) acc[j] = 0ULL;
        if (t > 0) {
#pragma unroll
            for (int i = 0; i < 4; i++) {
                const int kk = 4*lane + 128*i;
                ulonglong2 hv[8];
#pragma unroll
                for (int bl = 0; bl < 8; bl++)
                    hv[bl] = __ldcg((const ulonglong2*)(hsrc + (bq*8 + bl)*512 + kk));
#pragma unroll
                for (int g = 0; g < 8; g++) {
                    ulonglong2 wv = *(const ulonglong2*)(whh_s + (ggrp*8 + g)*512 + kk);
#pragma unroll
                    for (int bl = 0; bl < 8; bl++) {
                        acc[g*8+bl] = fma2(wv.x, hv[bl].x, acc[g*8+bl]);
                        acc[g*8+bl] = fma2(wv.y, hv[bl].y, acc[g*8+bl]);
                    }
                }
            }
        }
#pragma unroll
        for (int half = 0; half < 2; half++) {
            ull* v = acc + half*32;
#pragma unroll
            for (int s = 16; s > 0; s >>= 1) {
#pragma unroll
                for (int j = 0; j < 16; j++) {
                    if (j < s) {
                        bool up_ = (lane & s) != 0;
                        ull keep = up_ ? v[j + s] : v[j];
                        ull send = up_ ? v[j]     : v[j + s];
                        ull rec = __shfl_xor_sync(0xffffffffu, send, s);
                        v[j] = add2(keep, rec);
                    }
                }
            }
        }
        {
            float2 p0 = unpack2(acc[0]);
            float2 p1 = unpack2(acc[32]);
            gm[r0][bcol] = p0.x + p0.y + xv0;
            gm[r1][bcol] = p1.x + p1.y + xv1;
        }
        __syncthreads();

        if (tid < 128) {
            int jj = wid, b = lane;
            float ig = gm[jj][b], fg = gm[4+jj][b], gg = gm[8+jj][b], og = gm[12+jj][b];
            float c = c_reg;
            float ct = sigf(fg)*c + sigf(ig)*tanhf(gg);
            float ht = sigf(og)*tanhf(ct);
            float ub = ubin_s[b];
            float cn = ub*ct + (1.f-ub)*c;
            float hn = ub*ht + (1.f-ub)*hp;
            c_reg = cn;
            g_h[pp][b*512 + cta*4 + jj] = hn;
            if (t == TC-1) dout[(size_t)b*H_ + cta*4 + jj] = hn;
            cpart[jj][b] = cn * wuh_s[jj];
        }
        __syncthreads();
        if (tid < 32) {
            float pd = cpart[0][tid]+cpart[1][tid]+cpart[2][tid]+cpart[3][tid];
            atomicAdd(&g_uacc[(t + 1) & 3][tid*32], pd);
        }

        grid_bar(sense);
        sense ^= 1u;
    }
}

// zero all u accumulator phases for the next graph replay
__global__ void k4_reset() {
    g_uacc[threadIdx.x >> 5][(threadIdx.x & 31)*32] = 0.f;
}

extern "C" void kernel_launch(void* const* d_in, const int* in_sizes, int n_in,
                              void* d_out, int out_size) {
    const float* x     = (const float*)d_in[0];
    const float* cw    = (const float*)d_in[1];
    const float* cb    = (const float*)d_in[2];
    const float* gamma = (const float*)d_in[3];
    const float* beta  = (const float*)d_in[4];
    const float* mean  = (const float*)d_in[5];
    const float* var   = (const float*)d_in[6];
    const float* w_ih  = (const float*)d_in[7];
    const float* w_hh  = (const float*)d_in[8];
    const float* b_ih  = (const float*)d_in[9];
    const float* b_hh  = (const float*)d_in[10];
    const float* w_uh  = (const float*)d_in[11];
    const float* b_uh  = (const float*)d_in[12];
    float* dout = (float*)d_out;

    cudaFuncSetAttribute(k2_xproj, cudaFuncAttributeMaxDynamicSharedMemorySize, 49280);
    cudaFuncSetAttribute(k3_lstm,  cudaFuncAttributeMaxDynamicSharedMemorySize, 32768);

    k0_wt<<<640, 256>>>(cw);
    k1_conv<<<dim3(2, 128), 256>>>(x, cb, gamma, beta, mean, var);
    k2_xproj<<<dim3(16, TC), 256, 49280>>>(w_ih, b_ih, b_hh);
    k3_lstm<<<NCTA3, 256, 32768>>>(w_hh, w_uh, b_uh, dout);
    k4_reset<<<1, NCTA3>>>();
}

// round 11
// speedup vs baseline: 1.6198x; 1.0420x over previous
#include <cuda_runtime.h>
#include <math.h>

#define B_    32
#define T_IN  1024
#define CIN   128
#define F_    256
#define TC    510
#define H_    512
#define G4    2048
#define M_    (TC*B_)
#define NCTA3 128

__device__ float g_wt[5*CIN*F_];
__device__ float g_y[(size_t)M_*F_];
__device__ float g_xp[(size_t)TC*G4*B_];
__device__ float g_h[2][B_*H_];
__device__ float g_c[H_*B_];             // [unit][b]
__device__ float g_uacc[4][32*32];       // slot b at [phase][b*32]
__device__ float g_ust[NCTA3][2][32];    // per-CTA redundant (u, ubin)

typedef unsigned long long ull;

__device__ __forceinline__ ull fma2(ull a, ull b, ull c) {
    ull d;
    asm("fma.rn.f32x2 %0, %1, %2, %3;" : "=l"(d) : "l"(a), "l"(b), "l"(c));
    return d;
}
__device__ __forceinline__ ull add2(ull a, ull b) {
    ull d;
    asm("add.rn.f32x2 %0, %1, %2;" : "=l"(d) : "l"(a), "l"(b));
    return d;
}
__device__ __forceinline__ ull pack2(float lo, float hi) {
    ull d;
    asm("mov.b64 %0, {%1, %2};" : "=l"(d) : "f"(lo), "f"(hi));
    return d;
}
__device__ __forceinline__ float2 unpack2(ull v) {
    float2 r;
    asm("mov.b64 {%0, %1}, %2;" : "=f"(r.x), "=f"(r.y) : "l"(v));
    return r;
}

__global__ void k0_wt(const float* __restrict__ cw) {
    int k = blockIdx.x, f = threadIdx.x;
    g_wt[(size_t)k*F_ + f] = cw[((size_t)f*CIN + (k & 127))*5 + (k >> 7)];
}

__global__ __launch_bounds__(256) void k1_conv(
    const float* __restrict__ x, const float* __restrict__ cb,
    const float* __restrict__ gamma, const float* __restrict__ beta,
    const float* __restrict__ mean, const float* __restrict__ var)
{
    __shared__ float As[16][132];
    __shared__ float Bs[16][132];
    const int n0 = blockIdx.x * 128, m0 = blockIdx.y * 128;
    const int tid = threadIdx.x, tx = tid & 15, ty = tid >> 4;
    ull acc2[8][4];
#pragma unroll
    for (int i = 0; i < 8; i++)
#pragma unroll
        for (int j = 0; j < 4; j++) acc2[i][j] = 0ULL;

    for (int ks = 0; ks < 40; ks++) {
        const int k0 = ks * 16;
#pragma unroll
        for (int i = 0; i < 2; i++) {
            int idx = tid + i*256, ml = idx >> 2, kc = (idx & 3)*4;
            int m = m0 + ml;
            float4 v = make_float4(0.f,0.f,0.f,0.f);
            if (m < M_) {
                int t = m >> 5, b = m & 31, k = k0 + kc;
                v = *(const float4*)(x + ((size_t)b*T_IN + (size_t)(2*t + (k>>7)))*CIN + (k&127));
            }
            As[kc][ml]=v.x; As[kc+1][ml]=v.y; As[kc+2][ml]=v.z; As[kc+3][ml]=v.w;
        }
#pragma unroll
        for (int i = 0; i < 2; i++) {
            int idx = tid + i*256, kr = idx >> 5, nc = (idx & 31)*4;
            float4 v = *(const float4*)(g_wt + (size_t)(k0+kr)*F_ + n0 + nc);
            Bs[kr][nc]=v.x; Bs[kr][nc+1]=v.y; Bs[kr][nc+2]=v.z; Bs[kr][nc+3]=v.w;
        }
        __syncthreads();
#pragma unroll
        for (int kk = 0; kk < 16; kk++) {
            float a[8];
            *(float4*)&a[0] = *(const float4*)&As[kk][ty*8];
            *(float4*)&a[4] = *(const float4*)&As[kk][ty*8+4];
            ulonglong2 bL = *(const ulonglong2*)&Bs[kk][tx*8];
            ulonglong2 bH = *(const ulonglong2*)&Bs[kk][tx*8+4];
#pragma unroll
            for (int i = 0; i < 8; i++) {
                ull ai = pack2(a[i], a[i]);
                acc2[i][0] = fma2(ai, bL.x, acc2[i][0]);
                acc2[i][1] = fma2(ai, bL.y, acc2[i][1]);
                acc2[i][2] = fma2(ai, bH.x, acc2[i][2]);
                acc2[i][3] = fma2(ai, bH.y, acc2[i][3]);
            }
        }
        __syncthreads();
    }
    const int f0 = n0 + tx*8;
    float invs[8], adds[8], cbs[8];
#pragma unroll
    for (int j = 0; j < 8; j++) {
        float iv = gamma[f0+j] * rsqrtf(var[f0+j] + 1e-5f);
        invs[j] = iv; adds[j] = beta[f0+j] - mean[f0+j]*iv; cbs[j] = cb[f0+j];
    }
#pragma unroll
    for (int i = 0; i < 8; i++) {
        int m = m0 + ty*8 + i;
        if (m < M_) {
            float o[8];
#pragma unroll
            for (int j2 = 0; j2 < 4; j2++) {
                float2 p = unpack2(acc2[i][j2]);
                o[j2*2]   = fmaxf(p.x + cbs[j2*2],   0.f)*invs[j2*2]   + adds[j2*2];
                o[j2*2+1] = fmaxf(p.y + cbs[j2*2+1], 0.f)*invs[j2*2+1] + adds[j2*2+1];
            }
            *(float4*)(g_y + (size_t)m*F_ + f0)   = make_float4(o[0],o[1],o[2],o[3]);
            *(float4*)(g_y + (size_t)m*F_ + f0+4) = make_float4(o[4],o[5],o[6],o[7]);
        }
    }
}

__global__ __launch_bounds__(256) void k2_xproj(
    const float* __restrict__ w_ih, const float* __restrict__ b_ih,
    const float* __restrict__ b_hh)
{
    extern __shared__ float sm2[];
    float* Ys = sm2;            // 32 x 257
    float* Ws = sm2 + 32*257;   // 32 x 128
    const int t = blockIdx.y, g0 = blockIdx.x * 128;
    const int tid = threadIdx.x, tx = tid & 15, ty = tid >> 4;

    const float* src = g_y + (size_t)t*32*F_;
#pragma unroll
    for (int q = 0; q < 8; q++) {
        int idx = tid + q*256, b = idx >> 6, f4 = idx & 63;
        float4 v = *(const float4*)(src + (size_t)b*F_ + f4*4);
        float* d = Ys + b*257 + f4*4;
        d[0]=v.x; d[1]=v.y; d[2]=v.z; d[3]=v.w;
    }
    ull acc2[4][2];
#pragma unroll
    for (int j = 0; j < 4; j++) { acc2[j][0]=0ULL; acc2[j][1]=0ULL; }

    for (int fs = 0; fs < 8; fs++) {
        __syncthreads();
#pragma unroll
        for (int q = 0; q < 4; q++) {
            int idx = tid + q*256, g = idx >> 3, f4 = idx & 7;
            float4 v = *(const float4*)(w_ih + (size_t)(g0+g)*F_ + fs*32 + f4*4);
            Ws[(f4*4  )*128+g]=v.x; Ws[(f4*4+1)*128+g]=v.y;
            Ws[(f4*4+2)*128+g]=v.z; Ws[(f4*4+3)*128+g]=v.w;
        }
        __syncthreads();
#pragma unroll
        for (int fr = 0; fr < 32; fr++) {
            ulonglong2 aL = *(const ulonglong2*)(Ws + fr*128 + ty*8);
            ulonglong2 aH = *(const ulonglong2*)(Ws + fr*128 + ty*8 + 4);
            float y0 = Ys[(tx*2  )*257 + fs*32 + fr];
            float y1 = Ys[(tx*2+1)*257 + fs*32 + fr];
            ull y00 = pack2(y0, y0);
            ull y11 = pack2(y1, y1);
            acc2[0][0] = fma2(aL.x, y00, acc2[0][0]);
            acc2[1][0] = fma2(aL.y, y00, acc2[1][0]);
            acc2[2][0] = fma2(aH.x, y00, acc2[2][0]);
            acc2[3][0] = fma2(aH.y, y00, acc2[3][0]);
            acc2[0][1] = fma2(aL.x, y11, acc2[0][1]);
            acc2[1][1] = fma2(aL.y, y11, acc2[1][1]);
            acc2[2][1] = fma2(aH.x, y11, acc2[2][1]);
            acc2[3][1] = fma2(aH.y, y11, acc2[3][1]);
        }
    }
#pragma unroll
    for (int j2 = 0; j2 < 4; j2++) {
        int g = g0 + ty*8 + j2*2;
        float bias0 = b_ih[g]   + b_hh[g];
        float bias1 = b_ih[g+1] + b_hh[g+1];
        float2 p0 = unpack2(acc2[j2][0]);
        float2 p1 = unpack2(acc2[j2][1]);
        size_t base0 = ((size_t)t*G4 + g  )*B_ + tx*2;
        size_t base1 = ((size_t)t*G4 + g+1)*B_ + tx*2;
        g_xp[base0]   = p0.x + bias0;
        g_xp[base0+1] = p1.x + bias0;
        g_xp[base1]   = p0.y + bias1;
        g_xp[base1+1] = p1.y + bias1;
    }
}

__device__ __forceinline__ float sigf(float v) { return 1.f/(1.f + __expf(-v)); }

// zero u accumulator phases before the step chain (graph-replay determinism)
__global__ void kz_reset() {
    g_uacc[threadIdx.x >> 5][(threadIdx.x & 31)*32] = 0.f;
}

// one LSTM timestep: 128 CTAs x 256 threads; sync = kernel boundary
__global__ void __launch_bounds__(256, 1) k3step(
    int t,
    const float* __restrict__ w_hh, const float* __restrict__ w_uh,
    const float* __restrict__ b_uh, float* __restrict__ dout)
{
    extern __shared__ float dsm[];
    float* whh_s = dsm;             // 16 x 512 (32 KB)
    __shared__ float gm[16][33];
    __shared__ float u_s[32], ubin_s[32];
    __shared__ float cpart[4][32];
    __shared__ float wuh_s[4];

    const int cta = blockIdx.x, tid = threadIdx.x;
    const int lane = tid & 31, wid = tid >> 5;
    const int pp = t & 1, pq = pp ^ 1;
    const float* hsrc = g_h[pq];

#pragma unroll
    for (int q = 0; q < 8; q++) {
        int i4 = tid + q*256;
        int r = i4 >> 7, kk = (i4 & 127)*4;
        int grow = (r >> 2)*512 + cta*4 + (r & 3);
        *(float4*)(whh_s + r*512 + kk) = __ldcg((const float4*)(w_hh + (size_t)grow*H_ + kk));
    }
    if (tid < 4) wuh_s[tid] = w_uh[cta*4 + tid];
    const float buh = b_uh[0];

    const int ggrp = wid >> 2;
    const int bq   = wid & 3;
    const int bcol = bq*8 + (lane & 7);
    const int r0 = ggrp*8 + (lane >> 3);
    const int r1 = r0 + 4;
    const int gr0 = (r0 >> 2)*512 + cta*4 + (r0 & 3);
    const int gr1 = (r1 >> 2)*512 + cta*4 + (r1 & 3);

    // prefetches
    float xv0 = __ldcg(g_xp + ((size_t)t*G4 + gr0)*B_ + bcol);
    float xv1 = __ldcg(g_xp + ((size_t)t*G4 + gr1)*B_ + bcol);
    float hp = 0.f, c_in = 0.f;
    if (t > 0 && tid < 128) {
        hp   = __ldcg(hsrc + lane*512 + cta*4 + wid);
        c_in = __ldcg(g_c + (cta*4 + wid)*32 + lane);
    }

    // u-chain (warp 0, per-CTA redundant state)
    if (wid == 0) {
        if (t > 0) {
            float up = g_ust[cta][0][lane], ub = g_ust[cta][1][lane];
            float tot = __ldcg(&g_uacc[t & 3][lane*32]);
            float du = sigf(tot + buh);
            float un = ub*du + (1.f-ub)*(up + fminf(du, 1.f - up));
            float ubn = rintf(un);
            u_s[lane] = un; ubin_s[lane] = ubn;
            g_ust[cta][0][lane] = un; g_ust[cta][1][lane] = ubn;
        } else {
            u_s[lane] = 1.f; ubin_s[lane] = 1.f;
            g_ust[cta][0][lane] = 1.f; g_ust[cta][1][lane] = 1.f;
        }
    }
    if (cta == 0 && wid == 1) g_uacc[(t + 2) & 3][lane*32] = 0.f;
    __syncthreads();

    // matvec: h from L2
    ull acc[64];
#pragma unroll
    for (int j = 0; j < 64; j++) acc[j] = 0ULL;
    if (t > 0) {
#pragma unroll
        for (int i = 0; i < 4; i++) {
            const int kk = 4*lane + 128*i;
            ulonglong2 hv[8];
#pragma unroll
            for (int bl = 0; bl < 8; bl++)
                hv[bl] = __ldcg((const ulonglong2*)(hsrc + (bq*8 + bl)*512 + kk));
#pragma unroll
            for (int g = 0; g < 8; g++) {
                ulonglong2 wv = *(const ulonglong2*)(whh_s + (ggrp*8 + g)*512 + kk);
#pragma unroll
                for (int bl = 0; bl < 8; bl++) {
                    acc[g*8+bl] = fma2(wv.x, hv[bl].x, acc[g*8+bl]);
                    acc[g*8+bl] = fma2(wv.y, hv[bl].y, acc[g*8+bl]);
                }
            }
        }
    }
#pragma unroll
    for (int half = 0; half < 2; half++) {
        ull* v = acc + half*32;
#pragma unroll
        for (int s = 16; s > 0; s >>= 1) {
#pragma unroll
            for (int j = 0; j < 16; j++) {
                if (j < s) {
                    bool up_ = (lane & s) != 0;
                    ull keep = up_ ? v[j + s] : v[j];
                    ull send = up_ ? v[j]     : v[j + s];
                    ull rec = __shfl_xor_sync(0xffffffffu, send, s);
                    v[j] = add2(keep, rec);
                }
            }
        }
    }
    {
        float2 p0 = unpack2(acc[0]);
        float2 p1 = unpack2(acc[32]);
        gm[r0][bcol] = p0.x + p0.y + xv0;
        gm[r1][bcol] = p1.x + p1.y + xv1;
    }
    __syncthreads();

    if (tid < 128) {
        int jj = wid, b = lane;
        float ig = gm[jj][b], fg = gm[4+jj][b], gg = gm[8+jj][b], og = gm[12+jj][b];
        float c = c_in;
        float ct = sigf(fg)*c + sigf(ig)*tanhf(gg);
        float ht = sigf(og)*tanhf(ct);
        float ub = ubin_s[b];
        float cn = ub*ct + (1.f-ub)*c;
        float hn = ub*ht + (1.f-ub)*hp;
        g_h[pp][b*512 + cta*4 + jj] = hn;
        g_c[(cta*4 + jj)*32 + b] = cn;
        if (t == TC-1) dout[(size_t)b*H_ + cta*4 + jj] = hn;
        cpart[jj][b] = cn * wuh_s[jj];
    }
    __syncthreads();
    if (tid < 32) {
        float pd = cpart[0][tid]+cpart[1][tid]+cpart[2][tid]+cpart[3][tid];
        atomicAdd(&g_uacc[(t + 1) & 3][tid*32], pd);
    }
}

extern "C" void kernel_launch(void* const* d_in, const int* in_sizes, int n_in,
                              void* d_out, int out_size) {
    const float* x     = (const float*)d_in[0];
    const float* cw    = (const float*)d_in[1];
    const float* cb    = (const float*)d_in[2];
    const float* gamma = (const float*)d_in[3];
    const float* beta  = (const float*)d_in[4];
    const float* mean  = (const float*)d_in[5];
    const float* var   = (const float*)d_in[6];
    const float* w_ih  = (const float*)d_in[7];
    const float* w_hh  = (const float*)d_in[8];
    const float* b_ih  = (const float*)d_in[9];
    const float* b_hh  = (const float*)d_in[10];
    const float* w_uh  = (const float*)d_in[11];
    const float* b_uh  = (const float*)d_in[12];
    float* dout = (float*)d_out;

    cudaFuncSetAttribute(k2_xproj, cudaFuncAttributeMaxDynamicSharedMemorySize, 49280);

    k0_wt<<<640, 256>>>(cw);
    k1_conv<<<dim3(2, 128), 256>>>(x, cb, gamma, beta, mean, var);
    k2_xproj<<<dim3(16, TC), 256, 49280>>>(w_ih, b_ih, b_hh);
    kz_reset<<<1, NCTA3>>>();
    for (int t = 0; t < TC; ++t)
        k3step<<<NCTA3, 256, 32768>>>(t, w_hh, w_uh, b_uh, dout);
}

// round 12
// speedup vs baseline: 1.8820x; 1.1618x over previous
#include <cuda_runtime.h>
#include <math.h>

#define B_    32
#define T_IN  1024
#define CIN   128
#define F_    256
#define TC    510
#define H_    512
#define G4    2048
#define M_    (TC*B_)
#define NCTA3 128

__device__ float g_wt[5*CIN*F_];
__device__ float g_y[(size_t)M_*F_];
__device__ float g_xp[(size_t)TC*G4*B_];
__device__ float g_h[2][B_*H_];
__device__ float g_c[H_*B_];             // [unit][b]
__device__ float g_uacc[4][32*32];       // slot b at [phase][b*32]
__device__ float g_ust[NCTA3][2][32];    // per-CTA redundant (u, ubin)

typedef unsigned long long ull;

__device__ __forceinline__ ull fma2(ull a, ull b, ull c) {
    ull d;
    asm("fma.rn.f32x2 %0, %1, %2, %3;" : "=l"(d) : "l"(a), "l"(b), "l"(c));
    return d;
}
__device__ __forceinline__ ull add2(ull a, ull b) {
    ull d;
    asm("add.rn.f32x2 %0, %1, %2;" : "=l"(d) : "l"(a), "l"(b));
    return d;
}
__device__ __forceinline__ ull pack2(float lo, float hi) {
    ull d;
    asm("mov.b64 %0, {%1, %2};" : "=l"(d) : "f"(lo), "f"(hi));
    return d;
}
__device__ __forceinline__ float2 unpack2(ull v) {
    float2 r;
    asm("mov.b64 {%0, %1}, %2;" : "=f"(r.x), "=f"(r.y) : "l"(v));
    return r;
}

__global__ void k0_wt(const float* __restrict__ cw) {
    int k = blockIdx.x, f = threadIdx.x;
    g_wt[(size_t)k*F_ + f] = cw[((size_t)f*CIN + (k & 127))*5 + (k >> 7)];
    if (blockIdx.x == 0 && threadIdx.x < 128)
        g_uacc[threadIdx.x >> 5][(threadIdx.x & 31)*32] = 0.f;
}

__global__ __launch_bounds__(256) void k1_conv(
    const float* __restrict__ x, const float* __restrict__ cb,
    const float* __restrict__ gamma, const float* __restrict__ beta,
    const float* __restrict__ mean, const float* __restrict__ var)
{
    __shared__ float As[16][132];
    __shared__ float Bs[16][132];
    const int n0 = blockIdx.x * 128, m0 = blockIdx.y * 128;
    const int tid = threadIdx.x, tx = tid & 15, ty = tid >> 4;
    ull acc2[8][4];
#pragma unroll
    for (int i = 0; i < 8; i++)
#pragma unroll
        for (int j = 0; j < 4; j++) acc2[i][j] = 0ULL;

    for (int ks = 0; ks < 40; ks++) {
        const int k0 = ks * 16;
#pragma unroll
        for (int i = 0; i < 2; i++) {
            int idx = tid + i*256, ml = idx >> 2, kc = (idx & 3)*4;
            int m = m0 + ml;
            float4 v = make_float4(0.f,0.f,0.f,0.f);
            if (m < M_) {
                int t = m >> 5, b = m & 31, k = k0 + kc;
                v = *(const float4*)(x + ((size_t)b*T_IN + (size_t)(2*t + (k>>7)))*CIN + (k&127));
            }
            As[kc][ml]=v.x; As[kc+1][ml]=v.y; As[kc+2][ml]=v.z; As[kc+3][ml]=v.w;
        }
#pragma unroll
        for (int i = 0; i < 2; i++) {
            int idx = tid + i*256, kr = idx >> 5, nc = (idx & 31)*4;
            float4 v = *(const float4*)(g_wt + (size_t)(k0+kr)*F_ + n0 + nc);
            Bs[kr][nc]=v.x; Bs[kr][nc+1]=v.y; Bs[kr][nc+2]=v.z; Bs[kr][nc+3]=v.w;
        }
        __syncthreads();
#pragma unroll
        for (int kk = 0; kk < 16; kk++) {
            float a[8];
            *(float4*)&a[0] = *(const float4*)&As[kk][ty*8];
            *(float4*)&a[4] = *(const float4*)&As[kk][ty*8+4];
            ulonglong2 bL = *(const ulonglong2*)&Bs[kk][tx*8];
            ulonglong2 bH = *(const ulonglong2*)&Bs[kk][tx*8+4];
#pragma unroll
            for (int i = 0; i < 8; i++) {
                ull ai = pack2(a[i], a[i]);
                acc2[i][0] = fma2(ai, bL.x, acc2[i][0]);
                acc2[i][1] = fma2(ai, bL.y, acc2[i][1]);
                acc2[i][2] = fma2(ai, bH.x, acc2[i][2]);
                acc2[i][3] = fma2(ai, bH.y, acc2[i][3]);
            }
        }
        __syncthreads();
    }
    const int f0 = n0 + tx*8;
    float invs[8], adds[8], cbs[8];
#pragma unroll
    for (int j = 0; j < 8; j++) {
        float iv = gamma[f0+j] * rsqrtf(var[f0+j] + 1e-5f);
        invs[j] = iv; adds[j] = beta[f0+j] - mean[f0+j]*iv; cbs[j] = cb[f0+j];
    }
#pragma unroll
    for (int i = 0; i < 8; i++) {
        int m = m0 + ty*8 + i;
        if (m < M_) {
            float o[8];
#pragma unroll
            for (int j2 = 0; j2 < 4; j2++) {
                float2 p = unpack2(acc2[i][j2]);
                o[j2*2]   = fmaxf(p.x + cbs[j2*2],   0.f)*invs[j2*2]   + adds[j2*2];
                o[j2*2+1] = fmaxf(p.y + cbs[j2*2+1], 0.f)*invs[j2*2+1] + adds[j2*2+1];
            }
            *(float4*)(g_y + (size_t)m*F_ + f0)   = make_float4(o[0],o[1],o[2],o[3]);
            *(float4*)(g_y + (size_t)m*F_ + f0+4) = make_float4(o[4],o[5],o[6],o[7]);
        }
    }
}

__global__ __launch_bounds__(256) void k2_xproj(
    const float* __restrict__ w_ih, const float* __restrict__ b_ih,
    const float* __restrict__ b_hh)
{
    extern __shared__ float sm2[];
    float* Ys = sm2;            // 32 x 257
    float* Ws = sm2 + 32*257;   // 32 x 128
    const int t = blockIdx.y, g0 = blockIdx.x * 128;
    const int tid = threadIdx.x, tx = tid & 15, ty = tid >> 4;

    const float* src = g_y + (size_t)t*32*F_;
#pragma unroll
    for (int q = 0; q < 8; q++) {
        int idx = tid + q*256, b = idx >> 6, f4 = idx & 63;
        float4 v = *(const float4*)(src + (size_t)b*F_ + f4*4);
        float* d = Ys + b*257 + f4*4;
        d[0]=v.x; d[1]=v.y; d[2]=v.z; d[3]=v.w;
    }
    ull acc2[4][2];
#pragma unroll
    for (int j = 0; j < 4; j++) { acc2[j][0]=0ULL; acc2[j][1]=0ULL; }

    for (int fs = 0; fs < 8; fs++) {
        __syncthreads();
#pragma unroll
        for (int q = 0; q < 4; q++) {
            int idx = tid + q*256, g = idx >> 3, f4 = idx & 7;
            float4 v = *(const float4*)(w_ih + (size_t)(g0+g)*F_ + fs*32 + f4*4);
            Ws[(f4*4  )*128+g]=v.x; Ws[(f4*4+1)*128+g]=v.y;
            Ws[(f4*4+2)*128+g]=v.z; Ws[(f4*4+3)*128+g]=v.w;
        }
        __syncthreads();
#pragma unroll
        for (int fr = 0; fr < 32; fr++) {
            ulonglong2 aL = *(const ulonglong2*)(Ws + fr*128 + ty*8);
            ulonglong2 aH = *(const ulonglong2*)(Ws + fr*128 + ty*8 + 4);
            float y0 = Ys[(tx*2  )*257 + fs*32 + fr];
            float y1 = Ys[(tx*2+1)*257 + fs*32 + fr];
            ull y00 = pack2(y0, y0);
            ull y11 = pack2(y1, y1);
            acc2[0][0] = fma2(aL.x, y00, acc2[0][0]);
            acc2[1][0] = fma2(aL.y, y00, acc2[1][0]);
            acc2[2][0] = fma2(aH.x, y00, acc2[2][0]);
            acc2[3][0] = fma2(aH.y, y00, acc2[3][0]);
            acc2[0][1] = fma2(aL.x, y11, acc2[0][1]);
            acc2[1][1] = fma2(aL.y, y11, acc2[1][1]);
            acc2[2][1] = fma2(aH.x, y11, acc2[2][1]);
            acc2[3][1] = fma2(aH.y, y11, acc2[3][1]);
        }
    }
#pragma unroll
    for (int j2 = 0; j2 < 4; j2++) {
        int g = g0 + ty*8 + j2*2;
        float bias0 = b_ih[g]   + b_hh[g];
        float bias1 = b_ih[g+1] + b_hh[g+1];
        float2 p0 = unpack2(acc2[j2][0]);
        float2 p1 = unpack2(acc2[j2][1]);
        size_t base0 = ((size_t)t*G4 + g  )*B_ + tx*2;
        size_t base1 = ((size_t)t*G4 + g+1)*B_ + tx*2;
        g_xp[base0]   = p0.x + bias0;
        g_xp[base0+1] = p1.x + bias0;
        g_xp[base1]   = p0.y + bias1;
        g_xp[base1+1] = p1.y + bias1;
    }
}

__device__ __forceinline__ float sigf(float v) { return 1.f/(1.f + __expf(-v)); }

// one LSTM timestep; PDL: prologue (const data) overlaps previous step
__global__ void __launch_bounds__(256, 1) k3step(
    int t,
    const float* __restrict__ w_hh, const float* __restrict__ w_uh,
    const float* __restrict__ b_uh, float* __restrict__ dout)
{
    extern __shared__ float dsm[];
    float* whh_s = dsm;             // 16 x 512 (32 KB)
    __shared__ float gm[16][33];
    __shared__ float u_s[32], ubin_s[32];
    __shared__ float cpart[4][32];
    __shared__ float wuh_s[4];

    const int cta = blockIdx.x, tid = threadIdx.x;
    const int lane = tid & 31, wid = tid >> 5;
    const int pp = t & 1, pq = pp ^ 1;
    const float* hsrc = g_h[pq];

    // let the next step kernel launch immediately
    cudaTriggerProgrammaticLaunchCompletion();

    // ---- prologue: ONLY data constant w.r.t. the previous step ----
#pragma unroll
    for (int q = 0; q < 8; q++) {
        int i4 = tid + q*256;
        int r = i4 >> 7, kk = (i4 & 127)*4;
        int grow = (r >> 2)*512 + cta*4 + (r & 3);
        *(float4*)(whh_s + r*512 + kk) = __ldcg((const float4*)(w_hh + (size_t)grow*H_ + kk));
    }
    if (tid < 4) wuh_s[tid] = w_uh[cta*4 + tid];
    const float buh = b_uh[0];

    const int ggrp = wid >> 2;
    const int bq   = wid & 3;
    const int bcol = bq*8 + (lane & 7);
    const int r0 = ggrp*8 + (lane >> 3);
    const int r1 = r0 + 4;
    const int gr0 = (r0 >> 2)*512 + cta*4 + (r0 & 3);
    const int gr1 = (r1 >> 2)*512 + cta*4 + (r1 & 3);

    float xv0 = __ldcg(g_xp + ((size_t)t*G4 + gr0)*B_ + bcol);
    float xv1 = __ldcg(g_xp + ((size_t)t*G4 + gr1)*B_ + bcol);

    // ---- wait for previous step's writes ----
    cudaGridDependencySynchronize();

    float hp = 0.f, c_in = 0.f;
    if (t > 0 && tid < 128) {
        hp   = __ldcg(hsrc + lane*512 + cta*4 + wid);
        c_in = __ldcg(g_c + (cta*4 + wid)*32 + lane);
    }

    if (wid == 0) {
        if (t > 0) {
            float up = g_ust[cta][0][lane], ub = g_ust[cta][1][lane];
            float tot = __ldcg(&g_uacc[t & 3][lane*32]);
            float du = sigf(tot + buh);
            float un = ub*du + (1.f-ub)*(up + fminf(du, 1.f - up));
            float ubn = rintf(un);
            u_s[lane] = un; ubin_s[lane] = ubn;
            g_ust[cta][0][lane] = un; g_ust[cta][1][lane] = ubn;
        } else {
            u_s[lane] = 1.f; ubin_s[lane] = 1.f;
            g_ust[cta][0][lane] = 1.f; g_ust[cta][1][lane] = 1.f;
        }
    }
    if (cta == 0 && wid == 1) g_uacc[(t + 2) & 3][lane*32] = 0.f;
    __syncthreads();

    ull acc[64];
#pragma unroll
    for (int j = 0; j < 64; j++) acc[j] = 0ULL;
    if (t > 0) {
#pragma unroll
        for (int i = 0; i < 4; i++) {
            const int kk = 4*lane + 128*i;
            ulonglong2 hv[8];
#pragma unroll
            for (int bl = 0; bl < 8; bl++)
                hv[bl] = __ldcg((const ulonglong2*)(hsrc + (bq*8 + bl)*512 + kk));
#pragma unroll
            for (int g = 0; g < 8; g++) {
                ulonglong2 wv = *(const ulonglong2*)(whh_s + (ggrp*8 + g)*512 + kk);
#pragma unroll
                for (int bl = 0; bl < 8; bl++) {
                    acc[g*8+bl] = fma2(wv.x, hv[bl].x, acc[g*8+bl]);
                    acc[g*8+bl] = fma2(wv.y, hv[bl].y, acc[g*8+bl]);
                }
            }
        }
    }
#pragma unroll
    for (int half = 0; half < 2; half++) {
        ull* v = acc + half*32;
#pragma unroll
        for (int s = 16; s > 0; s >>= 1) {
#pragma unroll
            for (int j = 0; j < 16; j++) {
                if (j < s) {
                    bool up_ = (lane & s) != 0;
                    ull keep = up_ ? v[j + s] : v[j];
                    ull send = up_ ? v[j]     : v[j + s];
                    ull rec = __shfl_xor_sync(0xffffffffu, send, s);
                    v[j] = add2(keep, rec);
                }
            }
        }
    }
    {
        float2 p0 = unpack2(acc[0]);
        float2 p1 = unpack2(acc[32]);
        gm[r0][bcol] = p0.x + p0.y + xv0;
        gm[r1][bcol] = p1.x + p1.y + xv1;
    }
    __syncthreads();

    if (tid < 128) {
        int jj = wid, b = lane;
        float ig = gm[jj][b], fg = gm[4+jj][b], gg = gm[8+jj][b], og = gm[12+jj][b];
        float c = c_in;
        float ct = sigf(fg)*c + sigf(ig)*tanhf(gg);
        float ht = sigf(og)*tanhf(ct);
        float ub = ubin_s[b];
        float cn = ub*ct + (1.f-ub)*c;
        float hn = ub*ht + (1.f-ub)*hp;
        g_h[pp][b*512 + cta*4 + jj] = hn;
        g_c[(cta*4 + jj)*32 + b] = cn;
        if (t == TC-1) dout[(size_t)b*H_ + cta*4 + jj] = hn;
        cpart[jj][b] = cn * wuh_s[jj];
    }
    __syncthreads();
    if (tid < 32) {
        float pd = cpart[0][tid]+cpart[1][tid]+cpart[2][tid]+cpart[3][tid];
        atomicAdd(&g_uacc[(t + 1) & 3][tid*32], pd);
    }
}

extern "C" void kernel_launch(void* const* d_in, const int* in_sizes, int n_in,
                              void* d_out, int out_size) {
    const float* x     = (const float*)d_in[0];
    const float* cw    = (const float*)d_in[1];
    const float* cb    = (const float*)d_in[2];
    const float* gamma = (const float*)d_in[3];
    const float* beta  = (const float*)d_in[4];
    const float* mean  = (const float*)d_in[5];
    const float* var   = (const float*)d_in[6];
    const float* w_ih  = (const float*)d_in[7];
    const float* w_hh  = (const float*)d_in[8];
    const float* b_ih  = (const float*)d_in[9];
    const float* b_hh  = (const float*)d_in[10];
    const float* w_uh  = (const float*)d_in[11];
    const float* b_uh  = (const float*)d_in[12];
    float* dout = (float*)d_out;

    cudaFuncSetAttribute(k2_xproj, cudaFuncAttributeMaxDynamicSharedMemorySize, 49280);

    k0_wt<<<640, 256>>>(cw);
    k1_conv<<<dim3(2, 128), 256>>>(x, cb, gamma, beta, mean, var);
    k2_xproj<<<dim3(16, TC), 256, 49280>>>(w_ih, b_ih, b_hh);

    cudaLaunchAttribute at[1];
    at[0].id = cudaLaunchAttributeProgrammaticStreamSerialization;
    at[0].val.programmaticStreamSerializationAllowed = 1;
    cudaLaunchConfig_t cfg = {};
    cfg.gridDim = dim3(NCTA3, 1, 1);
    cfg.blockDim = dim3(256, 1, 1);
    cfg.dynamicSmemBytes = 32768;
    cfg.stream = 0;
    cfg.attrs = at;
    cfg.numAttrs = 1;
    for (int t = 0; t < TC; ++t)
        cudaLaunchKernelEx(&cfg, k3step, t, w_hh, w_uh, b_uh, dout);
}

// round 13
// speedup vs baseline: 1.8969x; 1.0079x over previous
#include <cuda_runtime.h>
#include <math.h>

#define B_    32
#define T_IN  1024
#define CIN   128
#define F_    256
#define TC    510
#define H_    512
#define G4    2048
#define M_    (TC*B_)
#define NC3   256

__device__ float g_wt[5*CIN*F_];
__device__ float g_y[(size_t)M_*F_];
__device__ float g_xp[(size_t)TC*G4*B_];
__device__ float g_h[2][B_*H_];
__device__ float g_c[H_*B_];             // [unit][b]
__device__ float g_uacc[4][32*32];       // slot b at [phase][b*32]
__device__ float g_ust[NC3][2][32];      // per-CTA redundant (u, ubin)

typedef unsigned long long ull;

__device__ __forceinline__ ull fma2(ull a, ull b, ull c) {
    ull d;
    asm("fma.rn.f32x2 %0, %1, %2, %3;" : "=l"(d) : "l"(a), "l"(b), "l"(c));
    return d;
}
__device__ __forceinline__ ull add2(ull a, ull b) {
    ull d;
    asm("add.rn.f32x2 %0, %1, %2;" : "=l"(d) : "l"(a), "l"(b));
    return d;
}
__device__ __forceinline__ ull pack2(float lo, float hi) {
    ull d;
    asm("mov.b64 %0, {%1, %2};" : "=l"(d) : "f"(lo), "f"(hi));
    return d;
}
__device__ __forceinline__ float2 unpack2(ull v) {
    float2 r;
    asm("mov.b64 {%0, %1}, %2;" : "=f"(r.x), "=f"(r.y) : "l"(v));
    return r;
}

__global__ void k0_wt(const float* __restrict__ cw) {
    int k = blockIdx.x, f = threadIdx.x;
    g_wt[(size_t)k*F_ + f] = cw[((size_t)f*CIN + (k & 127))*5 + (k >> 7)];
    if (blockIdx.x == 0 && threadIdx.x < 128)
        g_uacc[threadIdx.x >> 5][(threadIdx.x & 31)*32] = 0.f;
}

__global__ __launch_bounds__(256) void k1_conv(
    const float* __restrict__ x, const float* __restrict__ cb,
    const float* __restrict__ gamma, const float* __restrict__ beta,
    const float* __restrict__ mean, const float* __restrict__ var)
{
    __shared__ float As[16][132];
    __shared__ float Bs[16][132];
    const int n0 = blockIdx.x * 128, m0 = blockIdx.y * 128;
    const int tid = threadIdx.x, tx = tid & 15, ty = tid >> 4;
    ull acc2[8][4];
#pragma unroll
    for (int i = 0; i < 8; i++)
#pragma unroll
        for (int j = 0; j < 4; j++) acc2[i][j] = 0ULL;

    for (int ks = 0; ks < 40; ks++) {
        const int k0 = ks * 16;
#pragma unroll
        for (int i = 0; i < 2; i++) {
            int idx = tid + i*256, ml = idx >> 2, kc = (idx & 3)*4;
            int m = m0 + ml;
            float4 v = make_float4(0.f,0.f,0.f,0.f);
            if (m < M_) {
                int t = m >> 5, b = m & 31, k = k0 + kc;
                v = *(const float4*)(x + ((size_t)b*T_IN + (size_t)(2*t + (k>>7)))*CIN + (k&127));
            }
            As[kc][ml]=v.x; As[kc+1][ml]=v.y; As[kc+2][ml]=v.z; As[kc+3][ml]=v.w;
        }
#pragma unroll
        for (int i = 0; i < 2; i++) {
            int idx = tid + i*256, kr = idx >> 5, nc = (idx & 31)*4;
            float4 v = *(const float4*)(g_wt + (size_t)(k0+kr)*F_ + n0 + nc);
            Bs[kr][nc]=v.x; Bs[kr][nc+1]=v.y; Bs[kr][nc+2]=v.z; Bs[kr][nc+3]=v.w;
        }
        __syncthreads();
#pragma unroll
        for (int kk = 0; kk < 16; kk++) {
            float a[8];
            *(float4*)&a[0] = *(const float4*)&As[kk][ty*8];
            *(float4*)&a[4] = *(const float4*)&As[kk][ty*8+4];
            ulonglong2 bL = *(const ulonglong2*)&Bs[kk][tx*8];
            ulonglong2 bH = *(const ulonglong2*)&Bs[kk][tx*8+4];
#pragma unroll
            for (int i = 0; i < 8; i++) {
                ull ai = pack2(a[i], a[i]);
                acc2[i][0] = fma2(ai, bL.x, acc2[i][0]);
                acc2[i][1] = fma2(ai, bL.y, acc2[i][1]);
                acc2[i][2] = fma2(ai, bH.x, acc2[i][2]);
                acc2[i][3] = fma2(ai, bH.y, acc2[i][3]);
            }
        }
        __syncthreads();
    }
    const int f0 = n0 + tx*8;
    float invs[8], adds[8], cbs[8];
#pragma unroll
    for (int j = 0; j < 8; j++) {
        float iv = gamma[f0+j] * rsqrtf(var[f0+j] + 1e-5f);
        invs[j] = iv; adds[j] = beta[f0+j] - mean[f0+j]*iv; cbs[j] = cb[f0+j];
    }
#pragma unroll
    for (int i = 0; i < 8; i++) {
        int m = m0 + ty*8 + i;
        if (m < M_) {
            float o[8];
#pragma unroll
            for (int j2 = 0; j2 < 4; j2++) {
                float2 p = unpack2(acc2[i][j2]);
                o[j2*2]   = fmaxf(p.x + cbs[j2*2],   0.f)*invs[j2*2]   + adds[j2*2];
                o[j2*2+1] = fmaxf(p.y + cbs[j2*2+1], 0.f)*invs[j2*2+1] + adds[j2*2+1];
            }
            *(float4*)(g_y + (size_t)m*F_ + f0)   = make_float4(o[0],o[1],o[2],o[3]);
            *(float4*)(g_y + (size_t)m*F_ + f0+4) = make_float4(o[4],o[5],o[6],o[7]);
        }
    }
}

__global__ __launch_bounds__(256) void k2_xproj(
    const float* __restrict__ w_ih, const float* __restrict__ b_ih,
    const float* __restrict__ b_hh)
{
    extern __shared__ float sm2[];
    float* Ys = sm2;            // 32 x 257
    float* Ws = sm2 + 32*257;   // 32 x 128
    const int t = blockIdx.y, g0 = blockIdx.x * 128;
    const int tid = threadIdx.x, tx = tid & 15, ty = tid >> 4;

    const float* src = g_y + (size_t)t*32*F_;
#pragma unroll
    for (int q = 0; q < 8; q++) {
        int idx = tid + q*256, b = idx >> 6, f4 = idx & 63;
        float4 v = *(const float4*)(src + (size_t)b*F_ + f4*4);
        float* d = Ys + b*257 + f4*4;
        d[0]=v.x; d[1]=v.y; d[2]=v.z; d[3]=v.w;
    }
    ull acc2[4][2];
#pragma unroll
    for (int j = 0; j < 4; j++) { acc2[j][0]=0ULL; acc2[j][1]=0ULL; }

    for (int fs = 0; fs < 8; fs++) {
        __syncthreads();
#pragma unroll
        for (int q = 0; q < 4; q++) {
            int idx = tid + q*256, g = idx >> 3, f4 = idx & 7;
            float4 v = *(const float4*)(w_ih + (size_t)(g0+g)*F_ + fs*32 + f4*4);
            Ws[(f4*4  )*128+g]=v.x; Ws[(f4*4+1)*128+g]=v.y;
            Ws[(f4*4+2)*128+g]=v.z; Ws[(f4*4+3)*128+g]=v.w;
        }
        __syncthreads();
#pragma unroll
        for (int fr = 0; fr < 32; fr++) {
            ulonglong2 aL = *(const ulonglong2*)(Ws + fr*128 + ty*8);
            ulonglong2 aH = *(const ulonglong2*)(Ws + fr*128 + ty*8 + 4);
            float y0 = Ys[(tx*2  )*257 + fs*32 + fr];
            float y1 = Ys[(tx*2+1)*257 + fs*32 + fr];
            ull y00 = pack2(y0, y0);
            ull y11 = pack2(y1, y1);
            acc2[0][0] = fma2(aL.x, y00, acc2[0][0]);
            acc2[1][0] = fma2(aL.y, y00, acc2[1][0]);
            acc2[2][0] = fma2(aH.x, y00, acc2[2][0]);
            acc2[3][0] = fma2(aH.y, y00, acc2[3][0]);
            acc2[0][1] = fma2(aL.x, y11, acc2[0][1]);
            acc2[1][1] = fma2(aL.y, y11, acc2[1][1]);
            acc2[2][1] = fma2(aH.x, y11, acc2[2][1]);
            acc2[3][1] = fma2(aH.y, y11, acc2[3][1]);
        }
    }
#pragma unroll
    for (int j2 = 0; j2 < 4; j2++) {
        int g = g0 + ty*8 + j2*2;
        float bias0 = b_ih[g]   + b_hh[g];
        float bias1 = b_ih[g+1] + b_hh[g+1];
        float2 p0 = unpack2(acc2[j2][0]);
        float2 p1 = unpack2(acc2[j2][1]);
        size_t base0 = ((size_t)t*G4 + g  )*B_ + tx*2;
        size_t base1 = ((size_t)t*G4 + g+1)*B_ + tx*2;
        g_xp[base0]   = p0.x + bias0;
        g_xp[base0+1] = p1.x + bias0;
        g_xp[base1]   = p0.y + bias1;
        g_xp[base1+1] = p1.y + bias1;
    }
}

__device__ __forceinline__ float sigf(float v) { return 1.f/(1.f + __expf(-v)); }

// one LSTM timestep: 256 CTAs x 128 thr (2 units/CTA); PDL + 2-CTA/SM co-residency
__global__ void __launch_bounds__(128, 2) k3step(
    int t,
    const float* __restrict__ w_hh, const float* __restrict__ w_uh,
    const float* __restrict__ b_uh, float* __restrict__ dout)
{
    extern __shared__ float dsm[];
    float* whh_s = dsm;             // 8 x 512 (16 KB)
    __shared__ float gm[8][33];
    __shared__ float u_s[32], ubin_s[32];
    __shared__ float cpart[2][32];
    __shared__ float wuh_s[2];

    const int cta = blockIdx.x, tid = threadIdx.x;
    const int lane = tid & 31, wid = tid >> 5;      // wid = b-quad (0..3)
    const int pp = t & 1, pq = pp ^ 1;
    const float* hsrc = g_h[pq];

    cudaTriggerProgrammaticLaunchCompletion();

    // ---- prologue: data constant w.r.t. the previous step ----
#pragma unroll
    for (int q = 0; q < 8; q++) {
        int i4 = tid + q*128;                       // float4 idx 0..1023
        int r = i4 >> 7, kk = (i4 & 127)*4;         // r 0..7
        int grow = (r >> 1)*512 + cta*2 + (r & 1);
        *(float4*)(whh_s + r*512 + kk) = __ldcg((const float4*)(w_hh + (size_t)grow*H_ + kk));
    }
    if (tid < 2) wuh_s[tid] = w_uh[cta*2 + tid];
    const float buh = b_uh[0];

    const int bcol = wid*8 + (lane & 7);
    const int r0 = lane >> 3;                       // 0..3
    const int r1 = r0 + 4;                          // 4..7
    const int gr0 = (r0 >> 1)*512 + cta*2 + (r0 & 1);
    const int gr1 = (r1 >> 1)*512 + cta*2 + (r1 & 1);

    float xv0 = __ldcg(g_xp + ((size_t)t*G4 + gr0)*B_ + bcol);
    float xv1 = __ldcg(g_xp + ((size_t)t*G4 + gr1)*B_ + bcol);

    // ---- wait for previous step's grid ----
    cudaGridDependencySynchronize();

    float hp = 0.f, c_in = 0.f;
    if (t > 0 && tid < 64) {
        hp   = __ldcg(hsrc + (tid & 31)*512 + cta*2 + (tid >> 5));
        c_in = __ldcg(g_c + (cta*2 + (tid >> 5))*32 + (tid & 31));
    }

    if (wid == 0) {
        if (t > 0) {
            float up = g_ust[cta][0][lane], ub = g_ust[cta][1][lane];
            float tot = __ldcg(&g_uacc[t & 3][lane*32]);
            float du = sigf(tot + buh);
            float un = ub*du + (1.f-ub)*(up + fminf(du, 1.f - up));
            float ubn = rintf(un);
            u_s[lane] = un; ubin_s[lane] = ubn;
            g_ust[cta][0][lane] = un; g_ust[cta][1][lane] = ubn;
        } else {
            u_s[lane] = 1.f; ubin_s[lane] = 1.f;
            g_ust[cta][0][lane] = 1.f; g_ust[cta][1][lane] = 1.f;
        }
    }
    if (cta == 0 && wid == 1) g_uacc[(t + 2) & 3][lane*32] = 0.f;
    __syncthreads();

    // ---- matvec: 8 gate rows x 32 b; warp tile 8g x 8b; h from L2 ----
    ull acc[64];
#pragma unroll
    for (int j = 0; j < 64; j++) acc[j] = 0ULL;
    if (t > 0) {
#pragma unroll
        for (int i = 0; i < 4; i++) {
            const int kk = 4*lane + 128*i;
            ulonglong2 hv[8];
#pragma unroll
            for (int bl = 0; bl < 8; bl++)
                hv[bl] = __ldcg((const ulonglong2*)(hsrc + (wid*8 + bl)*512 + kk));
#pragma unroll
            for (int g = 0; g < 8; g++) {
                ulonglong2 wv = *(const ulonglong2*)(whh_s + g*512 + kk);
#pragma unroll
                for (int bl = 0; bl < 8; bl++) {
                    acc[g*8+bl] = fma2(wv.x, hv[bl].x, acc[g*8+bl]);
                    acc[g*8+bl] = fma2(wv.y, hv[bl].y, acc[g*8+bl]);
                }
            }
        }
    }
#pragma unroll
    for (int half = 0; half < 2; half++) {
        ull* v = acc + half*32;
#pragma unroll
        for (int s = 16; s > 0; s >>= 1) {
#pragma unroll
            for (int j = 0; j < 16; j++) {
                if (j < s) {
                    bool up_ = (lane & s) != 0;
                    ull keep = up_ ? v[j + s] : v[j];
                    ull send = up_ ? v[j]     : v[j + s];
                    ull rec = __shfl_xor_sync(0xffffffffu, send, s);
                    v[j] = add2(keep, rec);
                }
            }
        }
    }
    {
        float2 p0 = unpack2(acc[0]);
        float2 p1 = unpack2(acc[32]);
        gm[r0][bcol] = p0.x + p0.y + xv0;
        gm[r1][bcol] = p1.x + p1.y + xv1;
    }
    __syncthreads();

    // ---- cell update: 2 units x 32 batches ----
    if (tid < 64) {
        int jj = tid >> 5, b = tid & 31;
        float ig = gm[jj][b], fg = gm[2+jj][b], gg = gm[4+jj][b], og = gm[6+jj][b];
        float c = c_in;
        float ct = sigf(fg)*c + sigf(ig)*tanhf(gg);
        float ht = sigf(og)*tanhf(ct);
        float ub = ubin_s[b];
        float cn = ub*ct + (1.f-ub)*c;
        float hn = ub*ht + (1.f-ub)*hp;
        g_h[pp][b*512 + cta*2 + jj] = hn;
        g_c[(cta*2 + jj)*32 + b] = cn;
        if (t == TC-1) dout[(size_t)b*H_ + cta*2 + jj] = hn;
        cpart[jj][b] = cn * wuh_s[jj];
    }
    __syncthreads();
    if (tid < 32) {
        float pd = cpart[0][tid] + cpart[1][tid];
        atomicAdd(&g_uacc[(t + 1) & 3][tid*32], pd);
    }
}

extern "C" void kernel_launch(void* const* d_in, const int* in_sizes, int n_in,
                              void* d_out, int out_size) {
    const float* x     = (const float*)d_in[0];
    const float* cw    = (const float*)d_in[1];
    const float* cb    = (const float*)d_in[2];
    const float* gamma = (const float*)d_in[3];
    const float* beta  = (const float*)d_in[4];
    const float* mean  = (const float*)d_in[5];
    const float* var   = (const float*)d_in[6];
    const float* w_ih  = (const float*)d_in[7];
    const float* w_hh  = (const float*)d_in[8];
    const float* b_ih  = (const float*)d_in[9];
    const float* b_hh  = (const float*)d_in[10];
    const float* w_uh  = (const float*)d_in[11];
    const float* b_uh  = (const float*)d_in[12];
    float* dout = (float*)d_out;

    cudaFuncSetAttribute(k2_xproj, cudaFuncAttributeMaxDynamicSharedMemorySize, 49280);

    k0_wt<<<640, 256>>>(cw);
    k1_conv<<<dim3(2, 128), 256>>>(x, cb, gamma, beta, mean, var);
    k2_xproj<<<dim3(16, TC), 256, 49280>>>(w_ih, b_ih, b_hh);

    cudaLaunchAttribute at[1];
    at[0].id = cudaLaunchAttributeProgrammaticStreamSerialization;
    at[0].val.programmaticStreamSerializationAllowed = 1;
    cudaLaunchConfig_t cfg = {};
    cfg.gridDim = dim3(NC3, 1, 1);
    cfg.blockDim = dim3(128, 1, 1);
    cfg.dynamicSmemBytes = 16384;
    cfg.stream = 0;
    cfg.attrs = at;
    cfg.numAttrs = 1;
    for (int t = 0; t < TC; ++t)
        cudaLaunchKernelEx(&cfg, k3step, t, w_hh, w_uh, b_uh, dout);
}